// round 2
// baseline (speedup 1.0000x reference)
#include <cuda_runtime.h>
#include <cstdint>

#define BB 2
#define SLQ 2048
#define SLK 2048
#define DM 1024
#define NH 16
#define DH 64
#define MROWS (BB*SLQ)   // 4096

// Scratch (allocation-free rule: device globals)
__device__ float g_qh[NH*BB*SLQ*DH];
__device__ float g_kh[NH*BB*SLK*DH];
__device__ float g_vh[NH*BB*SLK*DH];
__device__ float g_oh[NH*BB*SLQ*DH];
__device__ float g_x [MROWS*DM];
__device__ int   g_mask_is_u8;

// ---------------------------------------------------------------------------
// Mask dtype sniffer: int32 0/1 words vs uint8 bools.
// If uint8 with ~half ones, some sampled 32-bit word will exceed 1.
// ---------------------------------------------------------------------------
__global__ void sniff_mask_kernel(const unsigned int* __restrict__ mw, int nwords)
{
    __shared__ int found;
    if (threadIdx.x == 0) found = 0;
    __syncthreads();
    int limit = nwords < 16384 ? nwords : 16384;
    for (int i = threadIdx.x; i < limit; i += blockDim.x)
        if (mw[i] > 1u) { found = 1; break; }
    __syncthreads();
    if (threadIdx.x == 0) g_mask_is_u8 = found;
}

// ---------------------------------------------------------------------------
// Projection GEMM: C[h,b,l,e] = sum_d X[b,l,d] * W[h,d,e]
// 128x128x8 fp32 tiled GEMM (256 threads, 8x8 per thread)
// ---------------------------------------------------------------------------
__global__ __launch_bounds__(256) void proj_kernel(
    const float* __restrict__ Xq, const float* __restrict__ Xk, const float* __restrict__ Xv,
    const float* __restrict__ Wq, const float* __restrict__ Wk, const float* __restrict__ Wv)
{
    const float* __restrict__ A;
    const float* __restrict__ W;
    float* __restrict__ C;
    if (blockIdx.z == 0)      { A = Xq; W = Wq; C = g_qh; }
    else if (blockIdx.z == 1) { A = Xk; W = Wk; C = g_kh; }
    else                      { A = Xv; W = Wv; C = g_vh; }

    __shared__ float As[8][128];
    __shared__ float Bs[8][128];

    const int t  = threadIdx.x;
    const int ty = t >> 4, tx = t & 15;
    const int mBase = blockIdx.y * 128;
    const int nBase = blockIdx.x * 128;

    const int arow = t >> 1, acol = (t & 1) * 4;
    const int brow = t >> 5, bcol = (t & 31) * 4;
    const int n  = nBase + bcol;
    const int hh = n >> 6, ee = n & 63;

    float acc[8][8];
    #pragma unroll
    for (int i = 0; i < 8; i++)
        #pragma unroll
        for (int j = 0; j < 8; j++) acc[i][j] = 0.f;

    for (int k0 = 0; k0 < DM; k0 += 8) {
        float4 av = *(const float4*)&A[(mBase + arow) * DM + k0 + acol];
        As[acol + 0][arow] = av.x;
        As[acol + 1][arow] = av.y;
        As[acol + 2][arow] = av.z;
        As[acol + 3][arow] = av.w;
        float4 bv = *(const float4*)&W[((hh * DM) + (k0 + brow)) * DH + ee];
        Bs[brow][bcol + 0] = bv.x;
        Bs[brow][bcol + 1] = bv.y;
        Bs[brow][bcol + 2] = bv.z;
        Bs[brow][bcol + 3] = bv.w;
        __syncthreads();
        #pragma unroll
        for (int kk = 0; kk < 8; kk++) {
            float a[8], b[8];
            float4 a0 = *(const float4*)&As[kk][ty * 8];
            float4 a1 = *(const float4*)&As[kk][ty * 8 + 4];
            a[0]=a0.x; a[1]=a0.y; a[2]=a0.z; a[3]=a0.w;
            a[4]=a1.x; a[5]=a1.y; a[6]=a1.z; a[7]=a1.w;
            float4 b0 = *(const float4*)&Bs[kk][tx * 8];
            float4 b1 = *(const float4*)&Bs[kk][tx * 8 + 4];
            b[0]=b0.x; b[1]=b0.y; b[2]=b0.z; b[3]=b0.w;
            b[4]=b1.x; b[5]=b1.y; b[6]=b1.z; b[7]=b1.w;
            #pragma unroll
            for (int i = 0; i < 8; i++)
                #pragma unroll
                for (int j = 0; j < 8; j++)
                    acc[i][j] += a[i] * b[j];
        }
        __syncthreads();
    }

    #pragma unroll
    for (int i = 0; i < 8; i++) {
        int m = mBase + ty * 8 + i;
        int bb = m >> 11, l = m & 2047;
        #pragma unroll
        for (int j = 0; j < 8; j++) {
            int nn = nBase + tx * 8 + j;
            int h = nn >> 6, e = nn & 63;
            C[(((h * BB + bb) * 2048) + l) * DH + e] = acc[i][j];
        }
    }
}

// Output projection GEMM: g_x[m,n] = sum_k Ocat[m,k]*Wo[k,n] + bo[n] + resid[m,n]
__global__ __launch_bounds__(256) void outproj_kernel(
    const float* __restrict__ resid, const float* __restrict__ Wo,
    const float* __restrict__ bo)
{
    __shared__ float As[8][128];
    __shared__ float Bs[8][128];

    const int t  = threadIdx.x;
    const int ty = t >> 4, tx = t & 15;
    const int mBase = blockIdx.y * 128;
    const int nBase = blockIdx.x * 128;

    const int arow = t >> 1, acol = (t & 1) * 4;
    const int brow = t >> 5, bcol = (t & 31) * 4;

    const int m_l = mBase + arow;
    const int ab = m_l >> 11, al = m_l & 2047;

    float acc[8][8];
    #pragma unroll
    for (int i = 0; i < 8; i++)
        #pragma unroll
        for (int j = 0; j < 8; j++) acc[i][j] = 0.f;

    for (int k0 = 0; k0 < DM; k0 += 8) {
        int kk4 = k0 + acol;
        int h = kk4 >> 6, e = kk4 & 63;
        float4 av = *(const float4*)&g_oh[(((h * BB + ab) * 2048) + al) * DH + e];
        As[acol + 0][arow] = av.x;
        As[acol + 1][arow] = av.y;
        As[acol + 2][arow] = av.z;
        As[acol + 3][arow] = av.w;
        float4 bv = *(const float4*)&Wo[(k0 + brow) * DM + nBase + bcol];
        Bs[brow][bcol + 0] = bv.x;
        Bs[brow][bcol + 1] = bv.y;
        Bs[brow][bcol + 2] = bv.z;
        Bs[brow][bcol + 3] = bv.w;
        __syncthreads();
        #pragma unroll
        for (int kk = 0; kk < 8; kk++) {
            float a[8], b[8];
            float4 a0 = *(const float4*)&As[kk][ty * 8];
            float4 a1 = *(const float4*)&As[kk][ty * 8 + 4];
            a[0]=a0.x; a[1]=a0.y; a[2]=a0.z; a[3]=a0.w;
            a[4]=a1.x; a[5]=a1.y; a[6]=a1.z; a[7]=a1.w;
            float4 b0 = *(const float4*)&Bs[kk][tx * 8];
            float4 b1 = *(const float4*)&Bs[kk][tx * 8 + 4];
            b[0]=b0.x; b[1]=b0.y; b[2]=b0.z; b[3]=b0.w;
            b[4]=b1.x; b[5]=b1.y; b[6]=b1.z; b[7]=b1.w;
            #pragma unroll
            for (int i = 0; i < 8; i++)
                #pragma unroll
                for (int j = 0; j < 8; j++)
                    acc[i][j] += a[i] * b[j];
        }
        __syncthreads();
    }

    #pragma unroll
    for (int i = 0; i < 8; i++) {
        int m = mBase + ty * 8 + i;
        #pragma unroll
        for (int j = 0; j < 8; j++) {
            int nn = nBase + tx * 8 + j;
            g_x[m * DM + nn] = acc[i][j] + bo[nn] + resid[m * DM + nn];
        }
    }
}

// ---------------------------------------------------------------------------
// Flash attention: per (h,b), BM=BN=64, online softmax. mask nonzero -> -inf.
// Mask dtype (int32 vs uint8) selected at runtime via g_mask_is_u8.
// ---------------------------------------------------------------------------
__global__ __launch_bounds__(256) void attn_kernel(const void* __restrict__ mask_raw)
{
    extern __shared__ float sm[];
    float* Qt = sm;                 // [64][64] transposed: Qt[d*64 + i]
    float* KP = sm + 64 * 64;       // [64][65]: K transposed, later P transposed
    float* Vs = KP + 65 * 64;       // [64][64]

    const int t  = threadIdx.x;
    const int ty = t >> 4, tx = t & 15;
    const int hb = blockIdx.y;           // h*BB + b
    const int b  = hb & 1;
    const int qBase = blockIdx.x * 64;
    const bool mask_u8 = (g_mask_is_u8 != 0);

    const float* __restrict__ Q = g_qh + (size_t)hb * SLQ * DH;
    const float* __restrict__ K = g_kh + (size_t)hb * SLK * DH;
    const float* __restrict__ V = g_vh + (size_t)hb * SLK * DH;
    float* __restrict__ O = g_oh + (size_t)hb * SLQ * DH;
    const unsigned char* __restrict__ mB8 =
        (const unsigned char*)mask_raw + (size_t)b * SLQ * SLK;
    const int* __restrict__ mB32 =
        (const int*)mask_raw + (size_t)b * SLQ * SLK;

    // Load Q tile transposed
    {
        const int row = (t >> 4), d0 = (t & 15) * 4;
        #pragma unroll
        for (int r = 0; r < 4; r++) {
            int rr = row + r * 16;
            float4 qv = *(const float4*)&Q[(qBase + rr) * DH + d0];
            Qt[(d0 + 0) * 64 + rr] = qv.x;
            Qt[(d0 + 1) * 64 + rr] = qv.y;
            Qt[(d0 + 2) * 64 + rr] = qv.z;
            Qt[(d0 + 3) * 64 + rr] = qv.w;
        }
    }

    float m_[4], l_[4], o_[4][4];
    #pragma unroll
    for (int i = 0; i < 4; i++) {
        m_[i] = -1e30f; l_[i] = 0.f;
        #pragma unroll
        for (int j = 0; j < 4; j++) o_[i][j] = 0.f;
    }

    const float scale = 0.125f;  // 1/sqrt(64)

    for (int kb = 0; kb < SLK; kb += 64) {
        {
            const int row = (t >> 4), d0 = (t & 15) * 4;
            #pragma unroll
            for (int r = 0; r < 4; r++) {
                int rr = row + r * 16;
                float4 kv = *(const float4*)&K[(kb + rr) * DH + d0];
                KP[(d0 + 0) * 65 + rr] = kv.x;
                KP[(d0 + 1) * 65 + rr] = kv.y;
                KP[(d0 + 2) * 65 + rr] = kv.z;
                KP[(d0 + 3) * 65 + rr] = kv.w;
                float4 vv = *(const float4*)&V[(kb + rr) * DH + d0];
                *(float4*)&Vs[rr * 64 + d0] = vv;
            }
        }
        __syncthreads();

        // S = Q K^T
        float s[4][4];
        #pragma unroll
        for (int i = 0; i < 4; i++)
            #pragma unroll
            for (int j = 0; j < 4; j++) s[i][j] = 0.f;
        #pragma unroll 4
        for (int d = 0; d < DH; d++) {
            float4 aq = *(const float4*)&Qt[d * 64 + ty * 4];
            float a[4] = {aq.x, aq.y, aq.z, aq.w};
            float bq[4];
            #pragma unroll
            for (int j = 0; j < 4; j++) bq[j] = KP[d * 65 + tx * 4 + j];
            #pragma unroll
            for (int i = 0; i < 4; i++)
                #pragma unroll
                for (int j = 0; j < 4; j++)
                    s[i][j] += a[i] * bq[j];
        }

        // mask + scale + online softmax
        float p[4][4];
        #pragma unroll
        for (int i = 0; i < 4; i++) {
            int qr = qBase + ty * 4 + i;
            int mv0, mv1, mv2, mv3;
            if (mask_u8) {
                uchar4 mk = *(const uchar4*)&mB8[(size_t)qr * SLK + kb + tx * 4];
                mv0 = mk.x; mv1 = mk.y; mv2 = mk.z; mv3 = mk.w;
            } else {
                int4 mk = *(const int4*)&mB32[(size_t)qr * SLK + kb + tx * 4];
                mv0 = mk.x; mv1 = mk.y; mv2 = mk.z; mv3 = mk.w;
            }
            s[i][0] = mv0 ? -1e30f : s[i][0] * scale;
            s[i][1] = mv1 ? -1e30f : s[i][1] * scale;
            s[i][2] = mv2 ? -1e30f : s[i][2] * scale;
            s[i][3] = mv3 ? -1e30f : s[i][3] * scale;
            float tm = fmaxf(fmaxf(s[i][0], s[i][1]), fmaxf(s[i][2], s[i][3]));
            #pragma unroll
            for (int sft = 8; sft >= 1; sft >>= 1)
                tm = fmaxf(tm, __shfl_xor_sync(0xffffffffu, tm, sft));
            float newm  = fmaxf(m_[i], tm);
            float alpha = __expf(m_[i] - newm);
            float rs = 0.f;
            #pragma unroll
            for (int j = 0; j < 4; j++) {
                p[i][j] = __expf(s[i][j] - newm);
                rs += p[i][j];
            }
            #pragma unroll
            for (int sft = 8; sft >= 1; sft >>= 1)
                rs += __shfl_xor_sync(0xffffffffu, rs, sft);
            l_[i] = l_[i] * alpha + rs;
            m_[i] = newm;
            #pragma unroll
            for (int j = 0; j < 4; j++) o_[i][j] *= alpha;
        }

        __syncthreads();  // done reading K tile; KP reused for P^T
        #pragma unroll
        for (int i = 0; i < 4; i++)
            #pragma unroll
            for (int j = 0; j < 4; j++)
                KP[(tx * 4 + j) * 65 + ty * 4 + i] = p[i][j];
        __syncthreads();

        // O += P V
        #pragma unroll 4
        for (int k = 0; k < 64; k++) {
            float a[4];
            #pragma unroll
            for (int i = 0; i < 4; i++) a[i] = KP[k * 65 + ty * 4 + i];
            float4 bv = *(const float4*)&Vs[k * 64 + tx * 4];
            float bj[4] = {bv.x, bv.y, bv.z, bv.w};
            #pragma unroll
            for (int i = 0; i < 4; i++)
                #pragma unroll
                for (int j = 0; j < 4; j++)
                    o_[i][j] += a[i] * bj[j];
        }
        __syncthreads();
    }

    #pragma unroll
    for (int i = 0; i < 4; i++) {
        float inv = 1.f / l_[i];
        #pragma unroll
        for (int j = 0; j < 4; j++)
            O[(qBase + ty * 4 + i) * DH + tx * 4 + j] = o_[i][j] * inv;
    }
}

// ---------------------------------------------------------------------------
// LayerNorm over last dim (1024), torch semantics: std ddof=1, eps on std.
// ---------------------------------------------------------------------------
__global__ __launch_bounds__(256) void ln_kernel(
    const float* __restrict__ gamma, const float* __restrict__ beta,
    float* __restrict__ out)
{
    __shared__ float red[8];
    const int row = blockIdx.x;
    const int t = threadIdx.x;
    const float* x = g_x + (size_t)row * DM;

    float4 v = *(const float4*)&x[t * 4];
    float s = v.x + v.y + v.z + v.w;
    #pragma unroll
    for (int sft = 16; sft >= 1; sft >>= 1)
        s += __shfl_xor_sync(0xffffffffu, s, sft);
    if ((t & 31) == 0) red[t >> 5] = s;
    __syncthreads();
    float tot = 0.f;
    #pragma unroll
    for (int w = 0; w < 8; w++) tot += red[w];
    float mean = tot * (1.0f / DM);
    __syncthreads();

    float d0 = v.x - mean, d1 = v.y - mean, d2 = v.z - mean, d3 = v.w - mean;
    float sq = d0 * d0 + d1 * d1 + d2 * d2 + d3 * d3;
    #pragma unroll
    for (int sft = 16; sft >= 1; sft >>= 1)
        sq += __shfl_xor_sync(0xffffffffu, sq, sft);
    if ((t & 31) == 0) red[t >> 5] = sq;
    __syncthreads();
    float sqt = 0.f;
    #pragma unroll
    for (int w = 0; w < 8; w++) sqt += red[w];
    float stdv = sqrtf(sqt * (1.0f / (DM - 1)));
    float inv = 1.0f / (stdv + 1e-3f);

    float4 g = *(const float4*)&gamma[t * 4];
    float4 be = *(const float4*)&beta[t * 4];
    float4 o;
    o.x = d0 * inv * g.x + be.x;
    o.y = d1 * inv * g.y + be.y;
    o.z = d2 * inv * g.z + be.z;
    o.w = d3 * inv * g.w + be.w;
    *(float4*)&out[(size_t)row * DM + t * 4] = o;
}

// ---------------------------------------------------------------------------
extern "C" void kernel_launch(void* const* d_in, const int* in_sizes, int n_in,
                              void* d_out, int out_size)
{
    const float* v_in  = (const float*)d_in[0];
    const float* k_in  = (const float*)d_in[1];
    const float* q_in  = (const float*)d_in[2];
    const void*  mask  = d_in[3];
    const float* w_q   = (const float*)d_in[4];
    const float* w_k   = (const float*)d_in[5];
    const float* w_v   = (const float*)d_in[6];
    const float* w_o   = (const float*)d_in[7];
    const float* b_o   = (const float*)d_in[8];
    const float* gamma = (const float*)d_in[9];
    const float* beta  = (const float*)d_in[10];
    float* out = (float*)d_out;

    const int attn_smem = (64 * 64 + 65 * 64 + 64 * 64) * sizeof(float); // 49,408 B
    cudaFuncSetAttribute(attn_kernel, cudaFuncAttributeMaxDynamicSharedMemorySize, 64 * 1024);

    // Mask element count: B*LQ*LK. Words available = bytes/4; if int32, words == count.
    // Sample up to 16K words (safe for either dtype since count >= 64K).
    sniff_mask_kernel<<<1, 256>>>((const unsigned int*)mask, 16384);
    proj_kernel<<<dim3(DM / 128, MROWS / 128, 3), 256>>>(q_in, k_in, v_in, w_q, w_k, w_v);
    attn_kernel<<<dim3(SLQ / 64, NH * BB), 256, attn_smem>>>(mask);
    outproj_kernel<<<dim3(DM / 128, MROWS / 128), 256>>>(k_in, w_o, b_o);
    ln_kernel<<<MROWS, 256>>>(gamma, beta, out);
}

// round 3
// speedup vs baseline: 2.5853x; 2.5853x over previous
#include <cuda_runtime.h>
#include <cstdint>

#define BB 2
#define SLQ 2048
#define SLK 2048
#define DM 1024
#define NH 16
#define DH 64
#define MROWS (BB*SLQ)   // 4096

// Scratch (allocation-free rule: device globals)
__device__ float g_qh[NH*BB*SLQ*DH];
__device__ float g_kh[NH*BB*SLK*DH];
__device__ float g_vh[NH*BB*SLK*DH];
__device__ float g_oh[NH*BB*SLQ*DH];
__device__ float g_x [MROWS*DM];
__device__ unsigned int g_mbits[BB*SLQ*(SLK/32)];
__device__ int g_mask_is_u8;

// ---------------------------------------------------------------------------
__device__ __forceinline__ unsigned int f2tf(float x) {
    unsigned int r;
    asm("cvt.rna.tf32.f32 %0, %1;" : "=r"(r) : "f"(x));
    return r;
}

__device__ __forceinline__ void mma_tf32(float* c,
    unsigned int a0, unsigned int a1, unsigned int a2, unsigned int a3,
    unsigned int b0, unsigned int b1)
{
    asm volatile(
        "mma.sync.aligned.m16n8k8.row.col.f32.tf32.tf32.f32 "
        "{%0,%1,%2,%3}, {%4,%5,%6,%7}, {%8,%9}, {%0,%1,%2,%3};"
        : "+f"(c[0]), "+f"(c[1]), "+f"(c[2]), "+f"(c[3])
        : "r"(a0), "r"(a1), "r"(a2), "r"(a3), "r"(b0), "r"(b1));
}

// ---------------------------------------------------------------------------
// Mask dtype sniffer: int32 0/1 words vs uint8 bools.
// ---------------------------------------------------------------------------
__global__ void sniff_mask_kernel(const unsigned int* __restrict__ mw, int nwords)
{
    __shared__ int found;
    if (threadIdx.x == 0) found = 0;
    __syncthreads();
    for (int i = threadIdx.x; i < nwords; i += blockDim.x)
        if (mw[i] > 1u) { found = 1; break; }
    __syncthreads();
    if (threadIdx.x == 0) g_mask_is_u8 = found;
}

// Pack mask into bits: bit=1 -> masked (-inf)
__global__ void pack_mask_kernel(const void* __restrict__ mraw)
{
    const int nwords = BB * SLQ * (SLK / 32);
    const int lane = threadIdx.x & 31;
    int gw = (blockIdx.x * blockDim.x + threadIdx.x) >> 5;
    const int stride = (gridDim.x * blockDim.x) >> 5;
    const bool u8 = (g_mask_is_u8 != 0);
    for (int w = gw; w < nwords; w += stride) {
        int idx = w * 32 + lane;
        int v = u8 ? (int)((const unsigned char*)mraw)[idx]
                   : ((const int*)mraw)[idx];
        unsigned int bits = __ballot_sync(0xffffffffu, v != 0);
        if (lane == 0) g_mbits[w] = bits;
    }
}

// ---------------------------------------------------------------------------
// Projection GEMM (tf32 mma): C[h,b,l,e] = sum_d X[b,l,d] * W[h,d,e]
// Block: M=128 x N=64 (one head), K-tile 32. 256 thr, 8 warps (4Mx2N),
// warp tile 32x32 = 2 m16 x 4 n8.
// ---------------------------------------------------------------------------
__global__ __launch_bounds__(256) void proj_kernel(
    const float* __restrict__ Xq, const float* __restrict__ Xk, const float* __restrict__ Xv,
    const float* __restrict__ Wq, const float* __restrict__ Wk, const float* __restrict__ Wv)
{
    const float* __restrict__ A;
    const float* __restrict__ W;
    float* __restrict__ C;
    if (blockIdx.z == 0)      { A = Xq; W = Wq; C = g_qh; }
    else if (blockIdx.z == 1) { A = Xk; W = Wk; C = g_kh; }
    else                      { A = Xv; W = Wv; C = g_vh; }

    __shared__ unsigned int As[128][36];
    __shared__ unsigned int Bs[32][68];

    const int t = threadIdx.x;
    const int warp = t >> 5, lane = t & 31;
    const int g = lane >> 2, tq = lane & 3;
    const int wm = warp >> 1, wn = warp & 1;
    const int mBase = blockIdx.y * 128;
    const int h = blockIdx.x;

    float acc[2][4][4];
    #pragma unroll
    for (int mt = 0; mt < 2; mt++)
        #pragma unroll
        for (int nt = 0; nt < 4; nt++)
            #pragma unroll
            for (int i = 0; i < 4; i++) acc[mt][nt][i] = 0.f;

    const int akq = (t & 7) * 4, amr = t >> 3;
    const int beq = (t & 15) * 4, bdr = t >> 4;

    for (int kt = 0; kt < DM; kt += 32) {
        #pragma unroll
        for (int bq = 0; bq < 4; bq++) {
            int m = amr + bq * 32;
            float4 av = *(const float4*)&A[(size_t)(mBase + m) * DM + kt + akq];
            As[m][akq + 0] = f2tf(av.x);
            As[m][akq + 1] = f2tf(av.y);
            As[m][akq + 2] = f2tf(av.z);
            As[m][akq + 3] = f2tf(av.w);
        }
        #pragma unroll
        for (int bq = 0; bq < 2; bq++) {
            int d = bdr + bq * 16;
            float4 bv = *(const float4*)&W[((size_t)h * DM + kt + d) * DH + beq];
            Bs[d][beq + 0] = f2tf(bv.x);
            Bs[d][beq + 1] = f2tf(bv.y);
            Bs[d][beq + 2] = f2tf(bv.z);
            Bs[d][beq + 3] = f2tf(bv.w);
        }
        __syncthreads();

        #pragma unroll
        for (int s = 0; s < 4; s++) {
            unsigned int bf[4][2];
            #pragma unroll
            for (int nt = 0; nt < 4; nt++) {
                int n = wn * 32 + nt * 8 + g;
                bf[nt][0] = Bs[s * 8 + tq][n];
                bf[nt][1] = Bs[s * 8 + tq + 4][n];
            }
            #pragma unroll
            for (int mt = 0; mt < 2; mt++) {
                int row = wm * 32 + mt * 16;
                unsigned int a0 = As[row + g][s * 8 + tq];
                unsigned int a1 = As[row + g + 8][s * 8 + tq];
                unsigned int a2 = As[row + g][s * 8 + tq + 4];
                unsigned int a3 = As[row + g + 8][s * 8 + tq + 4];
                #pragma unroll
                for (int nt = 0; nt < 4; nt++)
                    mma_tf32(acc[mt][nt], a0, a1, a2, a3, bf[nt][0], bf[nt][1]);
            }
        }
        __syncthreads();
    }

    // epilogue: C[((h*BB+b)*2048 + l)*64 + e]
    #pragma unroll
    for (int mt = 0; mt < 2; mt++) {
        int r0 = mBase + wm * 32 + mt * 16 + g;
        int r1 = r0 + 8;
        int b0i = r0 >> 11, l0 = r0 & 2047;
        int b1i = r1 >> 11, l1 = r1 & 2047;
        float* c0 = C + (((size_t)(h * BB + b0i) << 11) + l0) * DH;
        float* c1 = C + (((size_t)(h * BB + b1i) << 11) + l1) * DH;
        #pragma unroll
        for (int nt = 0; nt < 4; nt++) {
            int e = wn * 32 + nt * 8 + tq * 2;
            *(float2*)&c0[e] = make_float2(acc[mt][nt][0], acc[mt][nt][1]);
            *(float2*)&c1[e] = make_float2(acc[mt][nt][2], acc[mt][nt][3]);
        }
    }
}

// ---------------------------------------------------------------------------
// Output projection (tf32 mma): g_x = Ocat @ Wo + bo + resid
// Block M=128 x N=64, K-tile 32.
// ---------------------------------------------------------------------------
__global__ __launch_bounds__(256) void outproj_kernel(
    const float* __restrict__ resid, const float* __restrict__ Wo,
    const float* __restrict__ bo)
{
    __shared__ unsigned int As[128][36];
    __shared__ unsigned int Bs[32][68];

    const int t = threadIdx.x;
    const int warp = t >> 5, lane = t & 31;
    const int g = lane >> 2, tq = lane & 3;
    const int wm = warp >> 1, wn = warp & 1;
    const int mBase = blockIdx.y * 128;
    const int nBase = blockIdx.x * 64;

    float acc[2][4][4];
    #pragma unroll
    for (int mt = 0; mt < 2; mt++)
        #pragma unroll
        for (int nt = 0; nt < 4; nt++)
            #pragma unroll
            for (int i = 0; i < 4; i++) acc[mt][nt][i] = 0.f;

    const int akq = (t & 7) * 4, amr = t >> 3;
    const int beq = (t & 15) * 4, bdr = t >> 4;

    for (int kt = 0; kt < DM; kt += 32) {
        int kh = kt >> 6;                   // head index of this k-tile
        #pragma unroll
        for (int bq = 0; bq < 4; bq++) {
            int m = mBase + amr + bq * 32;
            int mb = m >> 11, ml = m & 2047;
            int k = kt + akq;
            int e = k & 63;
            float4 av = *(const float4*)&g_oh[(((size_t)(kh * BB + mb) << 11) + ml) * DH + e];
            As[amr + bq * 32][akq + 0] = f2tf(av.x);
            As[amr + bq * 32][akq + 1] = f2tf(av.y);
            As[amr + bq * 32][akq + 2] = f2tf(av.z);
            As[amr + bq * 32][akq + 3] = f2tf(av.w);
        }
        #pragma unroll
        for (int bq = 0; bq < 2; bq++) {
            int d = bdr + bq * 16;
            float4 bv = *(const float4*)&Wo[(size_t)(kt + d) * DM + nBase + beq];
            Bs[d][beq + 0] = f2tf(bv.x);
            Bs[d][beq + 1] = f2tf(bv.y);
            Bs[d][beq + 2] = f2tf(bv.z);
            Bs[d][beq + 3] = f2tf(bv.w);
        }
        __syncthreads();

        #pragma unroll
        for (int s = 0; s < 4; s++) {
            unsigned int bf[4][2];
            #pragma unroll
            for (int nt = 0; nt < 4; nt++) {
                int n = wn * 32 + nt * 8 + g;
                bf[nt][0] = Bs[s * 8 + tq][n];
                bf[nt][1] = Bs[s * 8 + tq + 4][n];
            }
            #pragma unroll
            for (int mt = 0; mt < 2; mt++) {
                int row = wm * 32 + mt * 16;
                unsigned int a0 = As[row + g][s * 8 + tq];
                unsigned int a1 = As[row + g + 8][s * 8 + tq];
                unsigned int a2 = As[row + g][s * 8 + tq + 4];
                unsigned int a3 = As[row + g + 8][s * 8 + tq + 4];
                #pragma unroll
                for (int nt = 0; nt < 4; nt++)
                    mma_tf32(acc[mt][nt], a0, a1, a2, a3, bf[nt][0], bf[nt][1]);
            }
        }
        __syncthreads();
    }

    #pragma unroll
    for (int mt = 0; mt < 2; mt++) {
        int r0 = mBase + wm * 32 + mt * 16 + g;
        int r1 = r0 + 8;
        #pragma unroll
        for (int nt = 0; nt < 4; nt++) {
            int n = nBase + wn * 32 + nt * 8 + tq * 2;
            float2 bb = *(const float2*)&bo[n];
            float2 rA = *(const float2*)&resid[(size_t)r0 * DM + n];
            float2 rB = *(const float2*)&resid[(size_t)r1 * DM + n];
            *(float2*)&g_x[(size_t)r0 * DM + n] =
                make_float2(acc[mt][nt][0] + bb.x + rA.x, acc[mt][nt][1] + bb.y + rA.y);
            *(float2*)&g_x[(size_t)r1 * DM + n] =
                make_float2(acc[mt][nt][2] + bb.x + rB.x, acc[mt][nt][3] + bb.y + rB.y);
        }
    }
}

// ---------------------------------------------------------------------------
// Flash attention (tf32 mma): per (h,b). Q tile 128 rows, KV tiles of 64.
// 8 warps, each owns m16 of Q rows. Online softmax in fp32 registers.
// ---------------------------------------------------------------------------
__global__ __launch_bounds__(256, 2) void attn_kernel()
{
    extern __shared__ unsigned int dynsm[];
    unsigned int (*Qs)[68] = (unsigned int (*)[68])dynsm;            // [128][68]
    unsigned int (*Ks)[68] = (unsigned int (*)[68])(dynsm + 128*68); // [64][68]
    unsigned int (*Vs)[68] = (unsigned int (*)[68])(dynsm + 192*68); // [64][68]

    const int t = threadIdx.x;
    const int warp = t >> 5, lane = t & 31;
    const int g = lane >> 2, tq = lane & 3;
    const int hb = blockIdx.y;
    const int b = hb & 1;
    const int qBase = blockIdx.x * 128;

    const float* __restrict__ Q = g_qh + (size_t)hb * SLQ * DH;
    const float* __restrict__ K = g_kh + (size_t)hb * SLK * DH;
    const float* __restrict__ V = g_vh + (size_t)hb * SLK * DH;
    float* __restrict__ O = g_oh + (size_t)hb * SLQ * DH;

    // Load Q tile (tf32-converted)
    {
        const int dq = (t & 15) * 4, r = t >> 4;
        #pragma unroll
        for (int bq = 0; bq < 8; bq++) {
            int rr = r + bq * 16;
            float4 qv = *(const float4*)&Q[(size_t)(qBase + rr) * DH + dq];
            Qs[rr][dq + 0] = f2tf(qv.x);
            Qs[rr][dq + 1] = f2tf(qv.y);
            Qs[rr][dq + 2] = f2tf(qv.z);
            Qs[rr][dq + 3] = f2tf(qv.w);
        }
    }

    float oc[8][4];
    #pragma unroll
    for (int dt = 0; dt < 8; dt++)
        #pragma unroll
        for (int i = 0; i < 4; i++) oc[dt][i] = 0.f;
    float m0 = -1e30f, m1 = -1e30f, l0 = 0.f, l1 = 0.f;

    const float scale = 0.125f;
    const int r0 = qBase + warp * 16 + g;
    const int r1 = r0 + 8;
    const unsigned int* mb0 = &g_mbits[((size_t)(b << 11) + r0) * 64];
    const unsigned int* mb1 = &g_mbits[((size_t)(b << 11) + r1) * 64];

    __syncthreads();

    for (int kb = 0; kb < SLK; kb += 64) {
        // load K, V tiles
        {
            const int dq = (t & 15) * 4, r = t >> 4;
            #pragma unroll
            for (int bq = 0; bq < 4; bq++) {
                int rr = r + bq * 16;
                float4 kv = *(const float4*)&K[(size_t)(kb + rr) * DH + dq];
                Ks[rr][dq + 0] = f2tf(kv.x);
                Ks[rr][dq + 1] = f2tf(kv.y);
                Ks[rr][dq + 2] = f2tf(kv.z);
                Ks[rr][dq + 3] = f2tf(kv.w);
                float4 vv = *(const float4*)&V[(size_t)(kb + rr) * DH + dq];
                Vs[rr][dq + 0] = f2tf(vv.x);
                Vs[rr][dq + 1] = f2tf(vv.y);
                Vs[rr][dq + 2] = f2tf(vv.z);
                Vs[rr][dq + 3] = f2tf(vv.w);
            }
        }
        __syncthreads();

        // S = Q K^T  (m16 x n64 per warp)
        float sc[8][4];
        #pragma unroll
        for (int nt = 0; nt < 8; nt++)
            #pragma unroll
            for (int i = 0; i < 4; i++) sc[nt][i] = 0.f;

        #pragma unroll
        for (int s = 0; s < 8; s++) {
            int row = warp * 16;
            unsigned int a0 = Qs[row + g][s * 8 + tq];
            unsigned int a1 = Qs[row + g + 8][s * 8 + tq];
            unsigned int a2 = Qs[row + g][s * 8 + tq + 4];
            unsigned int a3 = Qs[row + g + 8][s * 8 + tq + 4];
            #pragma unroll
            for (int nt = 0; nt < 8; nt++) {
                unsigned int b0 = Ks[nt * 8 + g][s * 8 + tq];
                unsigned int b1 = Ks[nt * 8 + g][s * 8 + tq + 4];
                mma_tf32(sc[nt], a0, a1, a2, a3, b0, b1);
            }
        }

        // mask + scale
        uint2 w0 = *(const uint2*)&mb0[kb >> 5];
        uint2 w1 = *(const uint2*)&mb1[kb >> 5];
        unsigned long long mm0 = (unsigned long long)w0.x | ((unsigned long long)w0.y << 32);
        unsigned long long mm1 = (unsigned long long)w1.x | ((unsigned long long)w1.y << 32);
        #pragma unroll
        for (int nt = 0; nt < 8; nt++) {
            int c0 = nt * 8 + tq * 2, c1 = c0 + 1;
            sc[nt][0] = ((mm0 >> c0) & 1ULL) ? -1e30f : sc[nt][0] * scale;
            sc[nt][1] = ((mm0 >> c1) & 1ULL) ? -1e30f : sc[nt][1] * scale;
            sc[nt][2] = ((mm1 >> c0) & 1ULL) ? -1e30f : sc[nt][2] * scale;
            sc[nt][3] = ((mm1 >> c1) & 1ULL) ? -1e30f : sc[nt][3] * scale;
        }

        // online softmax (rows r0, r1 per thread; quad = same row)
        float mx0 = -1e30f, mx1 = -1e30f;
        #pragma unroll
        for (int nt = 0; nt < 8; nt++) {
            mx0 = fmaxf(mx0, fmaxf(sc[nt][0], sc[nt][1]));
            mx1 = fmaxf(mx1, fmaxf(sc[nt][2], sc[nt][3]));
        }
        mx0 = fmaxf(mx0, __shfl_xor_sync(0xffffffffu, mx0, 1));
        mx0 = fmaxf(mx0, __shfl_xor_sync(0xffffffffu, mx0, 2));
        mx1 = fmaxf(mx1, __shfl_xor_sync(0xffffffffu, mx1, 1));
        mx1 = fmaxf(mx1, __shfl_xor_sync(0xffffffffu, mx1, 2));

        float newm0 = fmaxf(m0, mx0), newm1 = fmaxf(m1, mx1);
        float al0 = __expf(m0 - newm0), al1 = __expf(m1 - newm1);
        m0 = newm0; m1 = newm1;

        float rs0 = 0.f, rs1 = 0.f;
        #pragma unroll
        for (int nt = 0; nt < 8; nt++) {
            sc[nt][0] = __expf(sc[nt][0] - newm0);
            sc[nt][1] = __expf(sc[nt][1] - newm0);
            sc[nt][2] = __expf(sc[nt][2] - newm1);
            sc[nt][3] = __expf(sc[nt][3] - newm1);
            rs0 += sc[nt][0] + sc[nt][1];
            rs1 += sc[nt][2] + sc[nt][3];
        }
        rs0 += __shfl_xor_sync(0xffffffffu, rs0, 1);
        rs0 += __shfl_xor_sync(0xffffffffu, rs0, 2);
        rs1 += __shfl_xor_sync(0xffffffffu, rs1, 1);
        rs1 += __shfl_xor_sync(0xffffffffu, rs1, 2);
        l0 = l0 * al0 + rs0;
        l1 = l1 * al1 + rs1;

        #pragma unroll
        for (int dt = 0; dt < 8; dt++) {
            oc[dt][0] *= al0; oc[dt][1] *= al0;
            oc[dt][2] *= al1; oc[dt][3] *= al1;
        }

        // O += P V : convert P C-frag tile s -> A frag via shfl, then mma
        const int i0 = (g << 2) + (tq >> 1);
        const int i2 = i0 + 2;
        const bool odd = (tq & 1);
        #pragma unroll
        for (int s = 0; s < 8; s++) {
            float u00 = __shfl_sync(0xffffffffu, sc[s][0], i0);
            float u01 = __shfl_sync(0xffffffffu, sc[s][1], i0);
            float u10 = __shfl_sync(0xffffffffu, sc[s][2], i0);
            float u11 = __shfl_sync(0xffffffffu, sc[s][3], i0);
            float u20 = __shfl_sync(0xffffffffu, sc[s][0], i2);
            float u21 = __shfl_sync(0xffffffffu, sc[s][1], i2);
            float u30 = __shfl_sync(0xffffffffu, sc[s][2], i2);
            float u31 = __shfl_sync(0xffffffffu, sc[s][3], i2);
            unsigned int a0 = f2tf(odd ? u01 : u00);
            unsigned int a1 = f2tf(odd ? u11 : u10);
            unsigned int a2 = f2tf(odd ? u21 : u20);
            unsigned int a3 = f2tf(odd ? u31 : u30);
            #pragma unroll
            for (int dt = 0; dt < 8; dt++) {
                unsigned int b0 = Vs[s * 8 + tq][dt * 8 + g];
                unsigned int b1 = Vs[s * 8 + tq + 4][dt * 8 + g];
                mma_tf32(oc[dt], a0, a1, a2, a3, b0, b1);
            }
        }
        __syncthreads();
    }

    // epilogue
    float inv0 = 1.f / l0, inv1 = 1.f / l1;
    #pragma unroll
    for (int dt = 0; dt < 8; dt++) {
        int d = dt * 8 + tq * 2;
        *(float2*)&O[(size_t)r0 * DH + d] = make_float2(oc[dt][0] * inv0, oc[dt][1] * inv0);
        *(float2*)&O[(size_t)r1 * DH + d] = make_float2(oc[dt][2] * inv1, oc[dt][3] * inv1);
    }
}

// ---------------------------------------------------------------------------
// LayerNorm (ddof=1, eps on std)
// ---------------------------------------------------------------------------
__global__ __launch_bounds__(256) void ln_kernel(
    const float* __restrict__ gamma, const float* __restrict__ beta,
    float* __restrict__ out)
{
    __shared__ float red[8];
    const int row = blockIdx.x;
    const int t = threadIdx.x;
    const float* x = g_x + (size_t)row * DM;

    float4 v = *(const float4*)&x[t * 4];
    float s = v.x + v.y + v.z + v.w;
    #pragma unroll
    for (int sft = 16; sft >= 1; sft >>= 1)
        s += __shfl_xor_sync(0xffffffffu, s, sft);
    if ((t & 31) == 0) red[t >> 5] = s;
    __syncthreads();
    float tot = 0.f;
    #pragma unroll
    for (int w = 0; w < 8; w++) tot += red[w];
    float mean = tot * (1.0f / DM);
    __syncthreads();

    float d0 = v.x - mean, d1 = v.y - mean, d2 = v.z - mean, d3 = v.w - mean;
    float sq = d0 * d0 + d1 * d1 + d2 * d2 + d3 * d3;
    #pragma unroll
    for (int sft = 16; sft >= 1; sft >>= 1)
        sq += __shfl_xor_sync(0xffffffffu, sq, sft);
    if ((t & 31) == 0) red[t >> 5] = sq;
    __syncthreads();
    float sqt = 0.f;
    #pragma unroll
    for (int w = 0; w < 8; w++) sqt += red[w];
    float stdv = sqrtf(sqt * (1.0f / (DM - 1)));
    float inv = 1.0f / (stdv + 1e-3f);

    float4 gm = *(const float4*)&gamma[t * 4];
    float4 be = *(const float4*)&beta[t * 4];
    float4 o;
    o.x = d0 * inv * gm.x + be.x;
    o.y = d1 * inv * gm.y + be.y;
    o.z = d2 * inv * gm.z + be.z;
    o.w = d3 * inv * gm.w + be.w;
    *(float4*)&out[(size_t)row * DM + t * 4] = o;
}

// ---------------------------------------------------------------------------
extern "C" void kernel_launch(void* const* d_in, const int* in_sizes, int n_in,
                              void* d_out, int out_size)
{
    const float* v_in  = (const float*)d_in[0];
    const float* k_in  = (const float*)d_in[1];
    const float* q_in  = (const float*)d_in[2];
    const void*  mask  = d_in[3];
    const float* w_q   = (const float*)d_in[4];
    const float* w_k   = (const float*)d_in[5];
    const float* w_v   = (const float*)d_in[6];
    const float* w_o   = (const float*)d_in[7];
    const float* b_o   = (const float*)d_in[8];
    const float* gamma = (const float*)d_in[9];
    const float* beta  = (const float*)d_in[10];
    float* out = (float*)d_out;

    const int attn_smem = 256 * 68 * 4; // 69,632 B
    cudaFuncSetAttribute(attn_kernel, cudaFuncAttributeMaxDynamicSharedMemorySize, attn_smem);

    sniff_mask_kernel<<<1, 256>>>((const unsigned int*)mask, 16384);
    pack_mask_kernel<<<2048, 256>>>(mask);
    proj_kernel<<<dim3(NH, MROWS / 128, 3), 256>>>(q_in, k_in, v_in, w_q, w_k, w_v);
    attn_kernel<<<dim3(SLQ / 128, NH * BB), 256, attn_smem>>>();
    outproj_kernel<<<dim3(DM / 64, MROWS / 128), 256>>>(k_in, w_o, b_o);
    ln_kernel<<<MROWS, 256>>>(gamma, beta, out);
}

// round 4
// speedup vs baseline: 4.6498x; 1.7985x over previous
#include <cuda_runtime.h>
#include <cuda_fp16.h>
#include <cstdint>

#define BB 2
#define SLQ 2048
#define SLK 2048
#define DM 1024
#define NH 16
#define DH 64
#define MROWS (BB*SLQ)   // 4096

// Scratch (allocation-free rule: device globals)
__device__ __half g_qh[NH*BB*SLQ*DH];
__device__ __half g_kh[NH*BB*SLK*DH];
__device__ __half g_vh[NH*BB*SLK*DH];
__device__ __half g_oh[NH*BB*SLQ*DH];
__device__ __half g_xq[MROWS*DM];
__device__ __half g_xk[MROWS*DM];
__device__ __half g_xv[MROWS*DM];
__device__ __half g_wq[NH*DM*DH];
__device__ __half g_wk[NH*DM*DH];
__device__ __half g_wv[NH*DM*DH];
__device__ __half g_wo[DM*DM];
__device__ float  g_x [MROWS*DM];
__device__ unsigned int g_mbits[BB*SLQ*(SLK/32)];
__device__ int g_mask_is_u8;

// ---------------------------------------------------------------------------
__device__ __forceinline__ unsigned pack2(float a, float b) {
    __half2 h = __floats2half2_rn(a, b);
    return *(unsigned*)&h;
}

__device__ __forceinline__ void mma16816(float* c,
    unsigned a0, unsigned a1, unsigned a2, unsigned a3,
    unsigned b0, unsigned b1)
{
    asm volatile(
        "mma.sync.aligned.m16n8k16.row.col.f32.f16.f16.f32 "
        "{%0,%1,%2,%3}, {%4,%5,%6,%7}, {%8,%9}, {%0,%1,%2,%3};"
        : "+f"(c[0]), "+f"(c[1]), "+f"(c[2]), "+f"(c[3])
        : "r"(a0), "r"(a1), "r"(a2), "r"(a3), "r"(b0), "r"(b1));
}

__device__ __forceinline__ void ldsm4(unsigned& r0, unsigned& r1,
                                      unsigned& r2, unsigned& r3, unsigned addr)
{
    asm volatile("ldmatrix.sync.aligned.m8n8.x4.shared.b16 {%0,%1,%2,%3}, [%4];"
        : "=r"(r0), "=r"(r1), "=r"(r2), "=r"(r3) : "r"(addr));
}

__device__ __forceinline__ void ldsm4t(unsigned& r0, unsigned& r1,
                                       unsigned& r2, unsigned& r3, unsigned addr)
{
    asm volatile("ldmatrix.sync.aligned.m8n8.x4.trans.shared.b16 {%0,%1,%2,%3}, [%4];"
        : "=r"(r0), "=r"(r1), "=r"(r2), "=r"(r3) : "r"(addr));
}

// ---------------------------------------------------------------------------
__global__ void sniff_mask_kernel(const unsigned int* __restrict__ mw, int nwords)
{
    __shared__ int found;
    if (threadIdx.x == 0) found = 0;
    __syncthreads();
    for (int i = threadIdx.x; i < nwords; i += blockDim.x)
        if (mw[i] > 1u) { found = 1; break; }
    __syncthreads();
    if (threadIdx.x == 0) g_mask_is_u8 = found;
}

__global__ void pack_mask_kernel(const void* __restrict__ mraw)
{
    const int nwords = BB * SLQ * (SLK / 32);
    const int lane = threadIdx.x & 31;
    int gw = (blockIdx.x * blockDim.x + threadIdx.x) >> 5;
    const int stride = (gridDim.x * blockDim.x) >> 5;
    const bool u8 = (g_mask_is_u8 != 0);
    for (int w = gw; w < nwords; w += stride) {
        int idx = w * 32 + lane;
        int v = u8 ? (int)((const unsigned char*)mraw)[idx]
                   : ((const int*)mraw)[idx];
        unsigned int bits = __ballot_sync(0xffffffffu, v != 0);
        if (lane == 0) g_mbits[w] = bits;
    }
}

// fp32 -> fp16 prepack (n multiple of 4)
__global__ void f2h_kernel(const float* __restrict__ src, __half* __restrict__ dst, int n)
{
    int i = (blockIdx.x * blockDim.x + threadIdx.x) * 4;
    int stride = gridDim.x * blockDim.x * 4;
    for (; i < n; i += stride) {
        float4 v = *(const float4*)&src[i];
        unsigned u0 = pack2(v.x, v.y);
        unsigned u1 = pack2(v.z, v.w);
        *(uint2*)&dst[i] = make_uint2(u0, u1);
    }
}

// ---------------------------------------------------------------------------
// Projection GEMM (fp16 mma m16n8k16): C[h,b,l,e] = sum_d X[b,l,d]*W[h,d,e]
// Block 128x64 (one head n-slab), k-tile 64. 8 warps = 4m x 2n, warp 32x32.
// ---------------------------------------------------------------------------
__global__ __launch_bounds__(256) void proj_kernel()
{
    __shared__ __half As[128][72];
    __shared__ __half Bs[64][72];

    const __half* __restrict__ X;
    const __half* __restrict__ W;
    __half* __restrict__ C;
    if (blockIdx.z == 0)      { X = g_xq; W = g_wq; C = g_qh; }
    else if (blockIdx.z == 1) { X = g_xk; W = g_wk; C = g_kh; }
    else                      { X = g_xv; W = g_wv; C = g_vh; }

    const int t = threadIdx.x;
    const int warp = t >> 5, lane = t & 31;
    const int g = lane >> 2, tq = lane & 3;
    const int wm = warp >> 1, wn = warp & 1;
    const int mBase = blockIdx.y * 128;
    const int h = blockIdx.x;

    const int i8 = lane & 7, sel = lane >> 3;
    const int rowF = ((sel & 1) << 3) + i8;   // for A (non-trans) and B (trans)
    const int colF = (sel >> 1) << 3;
    const unsigned aBase = (unsigned)__cvta_generic_to_shared(&As[0][0])
                         + (rowF * 72 + colF) * 2;
    const unsigned bBase = (unsigned)__cvta_generic_to_shared(&Bs[0][0])
                         + (rowF * 72 + colF) * 2;

    float acc[2][4][4];
    #pragma unroll
    for (int mt = 0; mt < 2; mt++)
        #pragma unroll
        for (int nt = 0; nt < 4; nt++)
            #pragma unroll
            for (int i = 0; i < 4; i++) acc[mt][nt][i] = 0.f;

    for (int kt = 0; kt < DM; kt += 64) {
        // stage A: 128 rows x 64 halves = 1024 uint4
        #pragma unroll
        for (int it = 0; it < 4; it++) {
            int idx = t + it * 256;
            int row = idx >> 3, seg = (idx & 7) * 8;
            *(uint4*)&As[row][seg] =
                *(const uint4*)&X[(size_t)(mBase + row) * DM + kt + seg];
        }
        // stage B: 64 rows x 64 halves = 512 uint4
        #pragma unroll
        for (int it = 0; it < 2; it++) {
            int idx = t + it * 256;
            int row = idx >> 3, seg = (idx & 7) * 8;
            *(uint4*)&Bs[row][seg] =
                *(const uint4*)&W[((size_t)h * DM + kt + row) * DH + seg];
        }
        __syncthreads();

        #pragma unroll
        for (int ks = 0; ks < 4; ks++) {
            unsigned af[2][4];
            #pragma unroll
            for (int mt = 0; mt < 2; mt++)
                ldsm4(af[mt][0], af[mt][1], af[mt][2], af[mt][3],
                      aBase + ((wm * 32 + mt * 16) * 72 + ks * 16) * 2);
            #pragma unroll
            for (int ntp = 0; ntp < 2; ntp++) {
                unsigned b0, b1, b2, b3;
                ldsm4t(b0, b1, b2, b3,
                       bBase + ((ks * 16) * 72 + wn * 32 + ntp * 16) * 2);
                #pragma unroll
                for (int mt = 0; mt < 2; mt++) {
                    mma16816(acc[mt][ntp * 2],     af[mt][0], af[mt][1], af[mt][2], af[mt][3], b0, b1);
                    mma16816(acc[mt][ntp * 2 + 1], af[mt][0], af[mt][1], af[mt][2], af[mt][3], b2, b3);
                }
            }
        }
        __syncthreads();
    }

    // epilogue: C[((h*BB+b)*2048 + l)*64 + e] as half
    #pragma unroll
    for (int mt = 0; mt < 2; mt++) {
        int r0 = mBase + wm * 32 + mt * 16 + g;
        int r1 = r0 + 8;
        int b0i = r0 >> 11, l0 = r0 & 2047;
        int b1i = r1 >> 11, l1 = r1 & 2047;
        __half* c0 = C + (((size_t)(h * BB + b0i) << 11) + l0) * DH;
        __half* c1 = C + (((size_t)(h * BB + b1i) << 11) + l1) * DH;
        #pragma unroll
        for (int nt = 0; nt < 4; nt++) {
            int e = wn * 32 + nt * 8 + tq * 2;
            *(unsigned*)&c0[e] = pack2(acc[mt][nt][0], acc[mt][nt][1]);
            *(unsigned*)&c1[e] = pack2(acc[mt][nt][2], acc[mt][nt][3]);
        }
    }
}

// ---------------------------------------------------------------------------
// Output projection: g_x = Ocat @ Wo + bo + resid (fp32 out)
// ---------------------------------------------------------------------------
__global__ __launch_bounds__(256) void outproj_kernel(
    const float* __restrict__ resid, const float* __restrict__ bo)
{
    __shared__ __half As[128][72];
    __shared__ __half Bs[64][72];

    const int t = threadIdx.x;
    const int warp = t >> 5, lane = t & 31;
    const int g = lane >> 2, tq = lane & 3;
    const int wm = warp >> 1, wn = warp & 1;
    const int mBase = blockIdx.y * 128;
    const int nBase = blockIdx.x * 64;

    const int i8 = lane & 7, sel = lane >> 3;
    const int rowF = ((sel & 1) << 3) + i8;
    const int colF = (sel >> 1) << 3;
    const unsigned aBase = (unsigned)__cvta_generic_to_shared(&As[0][0])
                         + (rowF * 72 + colF) * 2;
    const unsigned bBase = (unsigned)__cvta_generic_to_shared(&Bs[0][0])
                         + (rowF * 72 + colF) * 2;

    float acc[2][4][4];
    #pragma unroll
    for (int mt = 0; mt < 2; mt++)
        #pragma unroll
        for (int nt = 0; nt < 4; nt++)
            #pragma unroll
            for (int i = 0; i < 4; i++) acc[mt][nt][i] = 0.f;

    for (int kt = 0; kt < DM; kt += 64) {
        const int kh = kt >> 6;   // head of this k-slab (exactly one per kt)
        #pragma unroll
        for (int it = 0; it < 4; it++) {
            int idx = t + it * 256;
            int row = idx >> 3, seg = (idx & 7) * 8;
            int m = mBase + row;
            int mb = m >> 11, ml = m & 2047;
            *(uint4*)&As[row][seg] =
                *(const uint4*)&g_oh[(((size_t)(kh * BB + mb) << 11) + ml) * DH + seg];
        }
        #pragma unroll
        for (int it = 0; it < 2; it++) {
            int idx = t + it * 256;
            int row = idx >> 3, seg = (idx & 7) * 8;
            *(uint4*)&Bs[row][seg] =
                *(const uint4*)&g_wo[(size_t)(kt + row) * DM + nBase + seg];
        }
        __syncthreads();

        #pragma unroll
        for (int ks = 0; ks < 4; ks++) {
            unsigned af[2][4];
            #pragma unroll
            for (int mt = 0; mt < 2; mt++)
                ldsm4(af[mt][0], af[mt][1], af[mt][2], af[mt][3],
                      aBase + ((wm * 32 + mt * 16) * 72 + ks * 16) * 2);
            #pragma unroll
            for (int ntp = 0; ntp < 2; ntp++) {
                unsigned b0, b1, b2, b3;
                ldsm4t(b0, b1, b2, b3,
                       bBase + ((ks * 16) * 72 + wn * 32 + ntp * 16) * 2);
                #pragma unroll
                for (int mt = 0; mt < 2; mt++) {
                    mma16816(acc[mt][ntp * 2],     af[mt][0], af[mt][1], af[mt][2], af[mt][3], b0, b1);
                    mma16816(acc[mt][ntp * 2 + 1], af[mt][0], af[mt][1], af[mt][2], af[mt][3], b2, b3);
                }
            }
        }
        __syncthreads();
    }

    #pragma unroll
    for (int mt = 0; mt < 2; mt++) {
        int r0 = mBase + wm * 32 + mt * 16 + g;
        int r1 = r0 + 8;
        #pragma unroll
        for (int nt = 0; nt < 4; nt++) {
            int n = nBase + wn * 32 + nt * 8 + tq * 2;
            float2 bb = *(const float2*)&bo[n];
            float2 rA = *(const float2*)&resid[(size_t)r0 * DM + n];
            float2 rB = *(const float2*)&resid[(size_t)r1 * DM + n];
            *(float2*)&g_x[(size_t)r0 * DM + n] =
                make_float2(acc[mt][nt][0] + bb.x + rA.x, acc[mt][nt][1] + bb.y + rA.y);
            *(float2*)&g_x[(size_t)r1 * DM + n] =
                make_float2(acc[mt][nt][2] + bb.x + rB.x, acc[mt][nt][3] + bb.y + rB.y);
        }
    }
}

// ---------------------------------------------------------------------------
// Flash attention (fp16 mma). Per (h,b): Q tile 128 rows, kv tiles of 64.
// 8 warps, each owns m16. Q fragments direct from global (half).
// ---------------------------------------------------------------------------
__global__ __launch_bounds__(256, 2) void attn_kernel()
{
    __shared__ __half Ks[64][72];
    __shared__ __half Vs[64][72];

    const int t = threadIdx.x;
    const int warp = t >> 5, lane = t & 31;
    const int g = lane >> 2, tq = lane & 3;
    const int hb = blockIdx.y;
    const int b = hb & 1;
    const int qBase = blockIdx.x * 128;

    const __half* __restrict__ Q = g_qh + (size_t)hb * SLQ * DH;
    const __half* __restrict__ K = g_kh + (size_t)hb * SLK * DH;
    const __half* __restrict__ V = g_vh + (size_t)hb * SLK * DH;
    __half* __restrict__ O = g_oh + (size_t)hb * SLQ * DH;

    const int r0 = qBase + warp * 16 + g;
    const int r1 = r0 + 8;

    // Q fragments straight from global (packed half2)
    unsigned qf[4][4];
    #pragma unroll
    for (int ks = 0; ks < 4; ks++) {
        qf[ks][0] = *(const unsigned*)&Q[(size_t)r0 * DH + ks * 16 + 2 * tq];
        qf[ks][1] = *(const unsigned*)&Q[(size_t)r1 * DH + ks * 16 + 2 * tq];
        qf[ks][2] = *(const unsigned*)&Q[(size_t)r0 * DH + ks * 16 + 8 + 2 * tq];
        qf[ks][3] = *(const unsigned*)&Q[(size_t)r1 * DH + ks * 16 + 8 + 2 * tq];
    }

    const int i8 = lane & 7, sel = lane >> 3;
    const int rowK = ((sel >> 1) << 3) + i8;   // K: non-trans tiles
    const int colK = (sel & 1) << 3;
    const int rowV = ((sel & 1) << 3) + i8;    // V: trans tiles
    const int colV = (sel >> 1) << 3;
    const unsigned kAddr0 = (unsigned)__cvta_generic_to_shared(&Ks[0][0])
                          + (rowK * 72 + colK) * 2;
    const unsigned vAddr0 = (unsigned)__cvta_generic_to_shared(&Vs[0][0])
                          + (rowV * 72 + colV) * 2;

    float oc[8][4];
    #pragma unroll
    for (int dt = 0; dt < 8; dt++)
        #pragma unroll
        for (int i = 0; i < 4; i++) oc[dt][i] = 0.f;
    float m0 = -1e30f, m1 = -1e30f, l0 = 0.f, l1 = 0.f;

    const float scale = 0.125f;
    const unsigned* mb0 = &g_mbits[((size_t)(b << 11) + r0) * 64];
    const unsigned* mb1 = &g_mbits[((size_t)(b << 11) + r1) * 64];

    for (int kb = 0; kb < SLK; kb += 64) {
        // stage K,V: 64 rows x 64 halves each = 512 uint4 each
        #pragma unroll
        for (int it = 0; it < 2; it++) {
            int idx = t + it * 256;
            int row = idx >> 3, seg = (idx & 7) * 8;
            *(uint4*)&Ks[row][seg] = *(const uint4*)&K[(size_t)(kb + row) * DH + seg];
            *(uint4*)&Vs[row][seg] = *(const uint4*)&V[(size_t)(kb + row) * DH + seg];
        }
        __syncthreads();

        // S = Q K^T  (m16 x n64 per warp)
        float sc[8][4];
        #pragma unroll
        for (int nt = 0; nt < 8; nt++)
            #pragma unroll
            for (int i = 0; i < 4; i++) sc[nt][i] = 0.f;

        #pragma unroll
        for (int ks = 0; ks < 4; ks++) {
            #pragma unroll
            for (int ntp = 0; ntp < 4; ntp++) {
                unsigned b0, b1, b2, b3;
                ldsm4(b0, b1, b2, b3, kAddr0 + (ntp * 16 * 72 + ks * 16) * 2);
                mma16816(sc[ntp * 2],     qf[ks][0], qf[ks][1], qf[ks][2], qf[ks][3], b0, b1);
                mma16816(sc[ntp * 2 + 1], qf[ks][0], qf[ks][1], qf[ks][2], qf[ks][3], b2, b3);
            }
        }

        // mask + scale
        uint2 w0 = *(const uint2*)&mb0[kb >> 5];
        uint2 w1 = *(const uint2*)&mb1[kb >> 5];
        unsigned long long mm0 = (unsigned long long)w0.x | ((unsigned long long)w0.y << 32);
        unsigned long long mm1 = (unsigned long long)w1.x | ((unsigned long long)w1.y << 32);
        #pragma unroll
        for (int nt = 0; nt < 8; nt++) {
            int c0 = nt * 8 + tq * 2, c1 = c0 + 1;
            sc[nt][0] = ((mm0 >> c0) & 1ULL) ? -1e30f : sc[nt][0] * scale;
            sc[nt][1] = ((mm0 >> c1) & 1ULL) ? -1e30f : sc[nt][1] * scale;
            sc[nt][2] = ((mm1 >> c0) & 1ULL) ? -1e30f : sc[nt][2] * scale;
            sc[nt][3] = ((mm1 >> c1) & 1ULL) ? -1e30f : sc[nt][3] * scale;
        }

        // online softmax (quad-pair reduction: lanes with same g share rows)
        float mx0 = -1e30f, mx1 = -1e30f;
        #pragma unroll
        for (int nt = 0; nt < 8; nt++) {
            mx0 = fmaxf(mx0, fmaxf(sc[nt][0], sc[nt][1]));
            mx1 = fmaxf(mx1, fmaxf(sc[nt][2], sc[nt][3]));
        }
        mx0 = fmaxf(mx0, __shfl_xor_sync(0xffffffffu, mx0, 1));
        mx0 = fmaxf(mx0, __shfl_xor_sync(0xffffffffu, mx0, 2));
        mx1 = fmaxf(mx1, __shfl_xor_sync(0xffffffffu, mx1, 1));
        mx1 = fmaxf(mx1, __shfl_xor_sync(0xffffffffu, mx1, 2));

        float newm0 = fmaxf(m0, mx0), newm1 = fmaxf(m1, mx1);
        float al0 = __expf(m0 - newm0), al1 = __expf(m1 - newm1);
        m0 = newm0; m1 = newm1;

        float rs0 = 0.f, rs1 = 0.f;
        #pragma unroll
        for (int nt = 0; nt < 8; nt++) {
            sc[nt][0] = __expf(sc[nt][0] - newm0);
            sc[nt][1] = __expf(sc[nt][1] - newm0);
            sc[nt][2] = __expf(sc[nt][2] - newm1);
            sc[nt][3] = __expf(sc[nt][3] - newm1);
            rs0 += sc[nt][0] + sc[nt][1];
            rs1 += sc[nt][2] + sc[nt][3];
        }
        rs0 += __shfl_xor_sync(0xffffffffu, rs0, 1);
        rs0 += __shfl_xor_sync(0xffffffffu, rs0, 2);
        rs1 += __shfl_xor_sync(0xffffffffu, rs1, 1);
        rs1 += __shfl_xor_sync(0xffffffffu, rs1, 2);
        l0 = l0 * al0 + rs0;
        l1 = l1 * al1 + rs1;

        #pragma unroll
        for (int dt = 0; dt < 8; dt++) {
            oc[dt][0] *= al0; oc[dt][1] *= al0;
            oc[dt][2] *= al1; oc[dt][3] *= al1;
        }

        // pack P into fp16 A fragments (no shuffles: layouts coincide)
        unsigned pf[8][2];
        #pragma unroll
        for (int nt = 0; nt < 8; nt++) {
            pf[nt][0] = pack2(sc[nt][0], sc[nt][1]);
            pf[nt][1] = pack2(sc[nt][2], sc[nt][3]);
        }

        // O += P V
        #pragma unroll
        for (int ks = 0; ks < 4; ks++) {
            unsigned a0 = pf[2 * ks][0], a1 = pf[2 * ks][1];
            unsigned a2 = pf[2 * ks + 1][0], a3 = pf[2 * ks + 1][1];
            #pragma unroll
            for (int dtp = 0; dtp < 4; dtp++) {
                unsigned b0, b1, b2, b3;
                ldsm4t(b0, b1, b2, b3, vAddr0 + (ks * 16 * 72 + dtp * 16) * 2);
                mma16816(oc[dtp * 2],     a0, a1, a2, a3, b0, b1);
                mma16816(oc[dtp * 2 + 1], a0, a1, a2, a3, b2, b3);
            }
        }
        __syncthreads();
    }

    // epilogue (half)
    float inv0 = 1.f / l0, inv1 = 1.f / l1;
    #pragma unroll
    for (int dt = 0; dt < 8; dt++) {
        int d = dt * 8 + tq * 2;
        *(unsigned*)&O[(size_t)r0 * DH + d] = pack2(oc[dt][0] * inv0, oc[dt][1] * inv0);
        *(unsigned*)&O[(size_t)r1 * DH + d] = pack2(oc[dt][2] * inv1, oc[dt][3] * inv1);
    }
}

// ---------------------------------------------------------------------------
// LayerNorm (ddof=1, eps on std)
// ---------------------------------------------------------------------------
__global__ __launch_bounds__(256) void ln_kernel(
    const float* __restrict__ gamma, const float* __restrict__ beta,
    float* __restrict__ out)
{
    __shared__ float red[8];
    const int row = blockIdx.x;
    const int t = threadIdx.x;
    const float* x = g_x + (size_t)row * DM;

    float4 v = *(const float4*)&x[t * 4];
    float s = v.x + v.y + v.z + v.w;
    #pragma unroll
    for (int sft = 16; sft >= 1; sft >>= 1)
        s += __shfl_xor_sync(0xffffffffu, s, sft);
    if ((t & 31) == 0) red[t >> 5] = s;
    __syncthreads();
    float tot = 0.f;
    #pragma unroll
    for (int w = 0; w < 8; w++) tot += red[w];
    float mean = tot * (1.0f / DM);
    __syncthreads();

    float d0 = v.x - mean, d1 = v.y - mean, d2 = v.z - mean, d3 = v.w - mean;
    float sq = d0 * d0 + d1 * d1 + d2 * d2 + d3 * d3;
    #pragma unroll
    for (int sft = 16; sft >= 1; sft >>= 1)
        sq += __shfl_xor_sync(0xffffffffu, sq, sft);
    if ((t & 31) == 0) red[t >> 5] = sq;
    __syncthreads();
    float sqt = 0.f;
    #pragma unroll
    for (int w = 0; w < 8; w++) sqt += red[w];
    float stdv = sqrtf(sqt * (1.0f / (DM - 1)));
    float inv = 1.0f / (stdv + 1e-3f);

    float4 gm = *(const float4*)&gamma[t * 4];
    float4 be = *(const float4*)&beta[t * 4];
    float4 o;
    o.x = d0 * inv * gm.x + be.x;
    o.y = d1 * inv * gm.y + be.y;
    o.z = d2 * inv * gm.z + be.z;
    o.w = d3 * inv * gm.w + be.w;
    *(float4*)&out[(size_t)row * DM + t * 4] = o;
}

// ---------------------------------------------------------------------------
extern "C" void kernel_launch(void* const* d_in, const int* in_sizes, int n_in,
                              void* d_out, int out_size)
{
    const float* v_in  = (const float*)d_in[0];
    const float* k_in  = (const float*)d_in[1];
    const float* q_in  = (const float*)d_in[2];
    const void*  mask  = d_in[3];
    const float* w_q   = (const float*)d_in[4];
    const float* w_k   = (const float*)d_in[5];
    const float* w_v   = (const float*)d_in[6];
    const float* w_o   = (const float*)d_in[7];
    const float* b_o   = (const float*)d_in[8];
    const float* gamma = (const float*)d_in[9];
    const float* beta  = (const float*)d_in[10];
    float* out = (float*)d_out;

    sniff_mask_kernel<<<1, 256>>>((const unsigned int*)mask, 16384);
    pack_mask_kernel<<<2048, 256>>>(mask);

    __half* d_xq; cudaGetSymbolAddress((void**)&d_xq, g_xq);
    __half* d_xk; cudaGetSymbolAddress((void**)&d_xk, g_xk);
    __half* d_xv; cudaGetSymbolAddress((void**)&d_xv, g_xv);
    __half* d_wq; cudaGetSymbolAddress((void**)&d_wq, g_wq);
    __half* d_wk; cudaGetSymbolAddress((void**)&d_wk, g_wk);
    __half* d_wv; cudaGetSymbolAddress((void**)&d_wv, g_wv);
    __half* d_wo; cudaGetSymbolAddress((void**)&d_wo, g_wo);

    f2h_kernel<<<2048, 256>>>(q_in, d_xq, MROWS * DM);
    f2h_kernel<<<2048, 256>>>(k_in, d_xk, MROWS * DM);
    f2h_kernel<<<2048, 256>>>(v_in, d_xv, MROWS * DM);
    f2h_kernel<<<1024, 256>>>(w_q, d_wq, NH * DM * DH);
    f2h_kernel<<<1024, 256>>>(w_k, d_wk, NH * DM * DH);
    f2h_kernel<<<1024, 256>>>(w_v, d_wv, NH * DM * DH);
    f2h_kernel<<<1024, 256>>>(w_o, d_wo, DM * DM);

    proj_kernel<<<dim3(NH, MROWS / 128, 3), 256>>>();
    attn_kernel<<<dim3(SLQ / 128, NH * BB), 256>>>();
    outproj_kernel<<<dim3(DM / 64, MROWS / 128), 256>>>(k_in, b_o);
    ln_kernel<<<MROWS, 256>>>(gamma, beta, out);
}

// round 5
// speedup vs baseline: 5.8998x; 1.2688x over previous
#include <cuda_runtime.h>
#include <cuda_fp16.h>
#include <cstdint>

#define BB 2
#define SLQ 2048
#define SLK 2048
#define DM 1024
#define NH 16
#define DH 64
#define MROWS (BB*SLQ)   // 4096

// Scratch (allocation-free rule: device globals)
__device__ __half g_qh[NH*BB*SLQ*DH];
__device__ __half g_kh[NH*BB*SLK*DH];
__device__ __half g_vh[NH*BB*SLK*DH];
__device__ __half g_oh[NH*BB*SLQ*DH];
__device__ __half g_xq[MROWS*DM];
__device__ __half g_xk[MROWS*DM];
__device__ __half g_xv[MROWS*DM];
__device__ __half g_wq[NH*DM*DH];
__device__ __half g_wk[NH*DM*DH];
__device__ __half g_wv[NH*DM*DH];
__device__ __half g_wo[DM*DM];
__device__ float  g_x [MROWS*DM];
__device__ unsigned int g_mbits[BB*SLQ*(SLK/32)];
__device__ int g_mask_is_u8;

// ---------------------------------------------------------------------------
__device__ __forceinline__ unsigned pack2(float a, float b) {
    __half2 h = __floats2half2_rn(a, b);
    return *(unsigned*)&h;
}

__device__ __forceinline__ void mma16816(float* c,
    unsigned a0, unsigned a1, unsigned a2, unsigned a3,
    unsigned b0, unsigned b1)
{
    asm volatile(
        "mma.sync.aligned.m16n8k16.row.col.f32.f16.f16.f32 "
        "{%0,%1,%2,%3}, {%4,%5,%6,%7}, {%8,%9}, {%0,%1,%2,%3};"
        : "+f"(c[0]), "+f"(c[1]), "+f"(c[2]), "+f"(c[3])
        : "r"(a0), "r"(a1), "r"(a2), "r"(a3), "r"(b0), "r"(b1));
}

__device__ __forceinline__ void ldsm4(unsigned& r0, unsigned& r1,
                                      unsigned& r2, unsigned& r3, unsigned addr)
{
    asm volatile("ldmatrix.sync.aligned.m8n8.x4.shared.b16 {%0,%1,%2,%3}, [%4];"
        : "=r"(r0), "=r"(r1), "=r"(r2), "=r"(r3) : "r"(addr));
}

__device__ __forceinline__ void ldsm4t(unsigned& r0, unsigned& r1,
                                       unsigned& r2, unsigned& r3, unsigned addr)
{
    asm volatile("ldmatrix.sync.aligned.m8n8.x4.trans.shared.b16 {%0,%1,%2,%3}, [%4];"
        : "=r"(r0), "=r"(r1), "=r"(r2), "=r"(r3) : "r"(addr));
}

__device__ __forceinline__ void cp16(unsigned smem, const void* gptr)
{
    asm volatile("cp.async.cg.shared.global [%0], [%1], 16;" :: "r"(smem), "l"(gptr));
}
__device__ __forceinline__ void cp_commit() { asm volatile("cp.async.commit_group;"); }
__device__ __forceinline__ void cp_wait0()  { asm volatile("cp.async.wait_group 0;"); }

// ---------------------------------------------------------------------------
__global__ void sniff_mask_kernel(const unsigned int* __restrict__ mw, int nwords)
{
    __shared__ int found;
    if (threadIdx.x == 0) found = 0;
    __syncthreads();
    for (int i = threadIdx.x; i < nwords; i += blockDim.x)
        if (mw[i] > 1u) { found = 1; break; }
    __syncthreads();
    if (threadIdx.x == 0) g_mask_is_u8 = found;
}

__global__ void pack_mask_kernel(const void* __restrict__ mraw)
{
    const int nwords = BB * SLQ * (SLK / 32);
    const int lane = threadIdx.x & 31;
    int gw = (blockIdx.x * blockDim.x + threadIdx.x) >> 5;
    const int stride = (gridDim.x * blockDim.x) >> 5;
    const bool u8 = (g_mask_is_u8 != 0);
    for (int w = gw; w < nwords; w += stride) {
        int idx = w * 32 + lane;
        int v = u8 ? (int)((const unsigned char*)mraw)[idx]
                   : ((const int*)mraw)[idx];
        unsigned int bits = __ballot_sync(0xffffffffu, v != 0);
        if (lane == 0) g_mbits[w] = bits;
    }
}

// Fused fp32 -> fp16 prepack for all 7 tensors. grid.y = region.
__global__ void f2h_all_kernel(
    const float* __restrict__ s0, const float* __restrict__ s1,
    const float* __restrict__ s2, const float* __restrict__ s3,
    const float* __restrict__ s4, const float* __restrict__ s5,
    const float* __restrict__ s6)
{
    const float* src;
    __half* dst;
    int n;
    switch (blockIdx.y) {
        case 0: src = s0; dst = g_xq; n = MROWS * DM; break;
        case 1: src = s1; dst = g_xk; n = MROWS * DM; break;
        case 2: src = s2; dst = g_xv; n = MROWS * DM; break;
        case 3: src = s3; dst = g_wq; n = NH * DM * DH; break;
        case 4: src = s4; dst = g_wk; n = NH * DM * DH; break;
        case 5: src = s5; dst = g_wv; n = NH * DM * DH; break;
        default: src = s6; dst = g_wo; n = DM * DM; break;
    }
    int i = (blockIdx.x * blockDim.x + threadIdx.x) * 4;
    int stride = gridDim.x * blockDim.x * 4;
    for (; i < n; i += stride) {
        float4 v = *(const float4*)&src[i];
        *(uint2*)&dst[i] = make_uint2(pack2(v.x, v.y), pack2(v.z, v.w));
    }
}

// ---------------------------------------------------------------------------
// Projection GEMM (fp16 mma): C[h,b,l,e] = sum_d X[b,l,d]*W[h,d,e]
// Block 128(M) x 128(N = 2 heads), k-tile 64, cp.async double buffered.
// 8 warps = 2m x 4n; warp tile 64x32.
// ---------------------------------------------------------------------------
#define ASZ (128*72)
#define BSZ (64*136)
#define GEMM_SMEM ((2*ASZ + 2*BSZ) * 2)

__global__ __launch_bounds__(256, 2) void proj_kernel()
{
    extern __shared__ __half dsm[];
    __half* Asm = dsm;
    __half* Bsm = dsm + 2 * ASZ;

    const __half* __restrict__ X;
    const __half* __restrict__ W;
    __half* __restrict__ C;
    if (blockIdx.z == 0)      { X = g_xq; W = g_wq; C = g_qh; }
    else if (blockIdx.z == 1) { X = g_xk; W = g_wk; C = g_kh; }
    else                      { X = g_xv; W = g_wv; C = g_vh; }

    const int t = threadIdx.x;
    const int warp = t >> 5, lane = t & 31;
    const int g = lane >> 2, tq = lane & 3;
    const int wm = warp >> 2, wn = warp & 3;
    const int mBase = blockIdx.y * 128;
    const int h0 = blockIdx.x * 2;

    const int i8 = lane & 7, sel = lane >> 3;
    const int rowF = ((sel & 1) << 3) + i8;
    const int colF = (sel >> 1) << 3;
    const unsigned aSm = (unsigned)__cvta_generic_to_shared(Asm);
    const unsigned bSm = (unsigned)__cvta_generic_to_shared(Bsm);

    float acc[4][4][4];
    #pragma unroll
    for (int mt = 0; mt < 4; mt++)
        #pragma unroll
        for (int nt = 0; nt < 4; nt++)
            #pragma unroll
            for (int i = 0; i < 4; i++) acc[mt][nt][i] = 0.f;

    const int arow = t >> 3, aseg = (t & 7) * 8;
    const int brow = t >> 4, bseg = (t & 15) * 8;

    auto stage = [&](int kt, int buf) {
        #pragma unroll
        for (int it = 0; it < 4; it++) {
            int row = arow + it * 32;
            cp16(aSm + ((buf * 128 + row) * 72 + aseg) * 2,
                 &X[(size_t)(mBase + row) * DM + kt + aseg]);
        }
        #pragma unroll
        for (int it = 0; it < 4; it++) {
            int row = brow + it * 16;
            int head = h0 + (bseg >> 6), e = bseg & 63;
            cp16(bSm + ((buf * 64 + row) * 136 + bseg) * 2,
                 &W[((size_t)head * DM + kt + row) * DH + e]);
        }
        cp_commit();
    };

    stage(0, 0);
    const int NKT = DM / 64;  // 16
    for (int it = 0; it < NKT; it++) {
        cp_wait0();
        __syncthreads();
        if (it + 1 < NKT) stage((it + 1) * 64, (it + 1) & 1);
        const int abuf = (it & 1) * 128, bbuf = (it & 1) * 64;

        #pragma unroll
        for (int ks = 0; ks < 4; ks++) {
            unsigned af[4][4];
            #pragma unroll
            for (int mt = 0; mt < 4; mt++)
                ldsm4(af[mt][0], af[mt][1], af[mt][2], af[mt][3],
                      aSm + ((abuf + wm * 64 + mt * 16 + rowF) * 72 + ks * 16 + colF) * 2);
            #pragma unroll
            for (int ntp = 0; ntp < 2; ntp++) {
                unsigned b0, b1, b2, b3;
                ldsm4t(b0, b1, b2, b3,
                       bSm + ((bbuf + ks * 16 + rowF) * 136 + wn * 32 + ntp * 16 + colF) * 2);
                #pragma unroll
                for (int mt = 0; mt < 4; mt++) {
                    mma16816(acc[mt][ntp * 2],     af[mt][0], af[mt][1], af[mt][2], af[mt][3], b0, b1);
                    mma16816(acc[mt][ntp * 2 + 1], af[mt][0], af[mt][1], af[mt][2], af[mt][3], b2, b3);
                }
            }
        }
    }

    // epilogue: C[((h*BB+b)*2048 + l)*64 + e] as half
    #pragma unroll
    for (int mt = 0; mt < 4; mt++) {
        int r0 = mBase + wm * 64 + mt * 16 + g;
        int r1 = r0 + 8;
        int b0i = r0 >> 11, l0 = r0 & 2047;
        int b1i = r1 >> 11, l1 = r1 & 2047;
        #pragma unroll
        for (int nt = 0; nt < 4; nt++) {
            int n = wn * 32 + nt * 8 + tq * 2;
            int head = h0 + (n >> 6), e = n & 63;
            __half* c0 = C + (((size_t)(head * BB + b0i) << 11) + l0) * DH;
            __half* c1 = C + (((size_t)(head * BB + b1i) << 11) + l1) * DH;
            *(unsigned*)&c0[e] = pack2(acc[mt][nt][0], acc[mt][nt][1]);
            *(unsigned*)&c1[e] = pack2(acc[mt][nt][2], acc[mt][nt][3]);
        }
    }
}

// ---------------------------------------------------------------------------
// Output projection: g_x = Ocat @ Wo + bo + resid (fp32 out)
// Block 128 x 128, cp.async double buffered.
// ---------------------------------------------------------------------------
__global__ __launch_bounds__(256, 2) void outproj_kernel(
    const float* __restrict__ resid, const float* __restrict__ bo)
{
    extern __shared__ __half dsm[];
    __half* Asm = dsm;
    __half* Bsm = dsm + 2 * ASZ;

    const int t = threadIdx.x;
    const int warp = t >> 5, lane = t & 31;
    const int g = lane >> 2, tq = lane & 3;
    const int wm = warp >> 2, wn = warp & 3;
    const int mBase = blockIdx.y * 128;
    const int nBase = blockIdx.x * 128;

    const int i8 = lane & 7, sel = lane >> 3;
    const int rowF = ((sel & 1) << 3) + i8;
    const int colF = (sel >> 1) << 3;
    const unsigned aSm = (unsigned)__cvta_generic_to_shared(Asm);
    const unsigned bSm = (unsigned)__cvta_generic_to_shared(Bsm);

    float acc[4][4][4];
    #pragma unroll
    for (int mt = 0; mt < 4; mt++)
        #pragma unroll
        for (int nt = 0; nt < 4; nt++)
            #pragma unroll
            for (int i = 0; i < 4; i++) acc[mt][nt][i] = 0.f;

    const int arow = t >> 3, aseg = (t & 7) * 8;
    const int brow = t >> 4, bseg = (t & 15) * 8;

    auto stage = [&](int kt, int buf) {
        const int kh = kt >> 6;
        #pragma unroll
        for (int it = 0; it < 4; it++) {
            int row = arow + it * 32;
            int m = mBase + row;
            int mb = m >> 11, ml = m & 2047;
            cp16(aSm + ((buf * 128 + row) * 72 + aseg) * 2,
                 &g_oh[(((size_t)(kh * BB + mb) << 11) + ml) * DH + aseg]);
        }
        #pragma unroll
        for (int it = 0; it < 4; it++) {
            int row = brow + it * 16;
            cp16(bSm + ((buf * 64 + row) * 136 + bseg) * 2,
                 &g_wo[(size_t)(kt + row) * DM + nBase + bseg]);
        }
        cp_commit();
    };

    stage(0, 0);
    const int NKT = DM / 64;
    for (int it = 0; it < NKT; it++) {
        cp_wait0();
        __syncthreads();
        if (it + 1 < NKT) stage((it + 1) * 64, (it + 1) & 1);
        const int abuf = (it & 1) * 128, bbuf = (it & 1) * 64;

        #pragma unroll
        for (int ks = 0; ks < 4; ks++) {
            unsigned af[4][4];
            #pragma unroll
            for (int mt = 0; mt < 4; mt++)
                ldsm4(af[mt][0], af[mt][1], af[mt][2], af[mt][3],
                      aSm + ((abuf + wm * 64 + mt * 16 + rowF) * 72 + ks * 16 + colF) * 2);
            #pragma unroll
            for (int ntp = 0; ntp < 2; ntp++) {
                unsigned b0, b1, b2, b3;
                ldsm4t(b0, b1, b2, b3,
                       bSm + ((bbuf + ks * 16 + rowF) * 136 + wn * 32 + ntp * 16 + colF) * 2);
                #pragma unroll
                for (int mt = 0; mt < 4; mt++) {
                    mma16816(acc[mt][ntp * 2],     af[mt][0], af[mt][1], af[mt][2], af[mt][3], b0, b1);
                    mma16816(acc[mt][ntp * 2 + 1], af[mt][0], af[mt][1], af[mt][2], af[mt][3], b2, b3);
                }
            }
        }
    }

    #pragma unroll
    for (int mt = 0; mt < 4; mt++) {
        int r0 = mBase + wm * 64 + mt * 16 + g;
        int r1 = r0 + 8;
        #pragma unroll
        for (int nt = 0; nt < 4; nt++) {
            int n = nBase + wn * 32 + nt * 8 + tq * 2;
            float2 bb = *(const float2*)&bo[n];
            float2 rA = *(const float2*)&resid[(size_t)r0 * DM + n];
            float2 rB = *(const float2*)&resid[(size_t)r1 * DM + n];
            *(float2*)&g_x[(size_t)r0 * DM + n] =
                make_float2(acc[mt][nt][0] + bb.x + rA.x, acc[mt][nt][1] + bb.y + rA.y);
            *(float2*)&g_x[(size_t)r1 * DM + n] =
                make_float2(acc[mt][nt][2] + bb.x + rB.x, acc[mt][nt][3] + bb.y + rB.y);
        }
    }
}

// ---------------------------------------------------------------------------
// Flash attention (fp16 mma, cp.async double buffered K/V).
// Per (h,b): Q tile 128 rows, kv tiles of 64. 8 warps x m16.
// ---------------------------------------------------------------------------
__global__ __launch_bounds__(256, 2) void attn_kernel()
{
    __shared__ __half Ks[2][64][72];
    __shared__ __half Vs[2][64][72];

    const int t = threadIdx.x;
    const int warp = t >> 5, lane = t & 31;
    const int g = lane >> 2, tq = lane & 3;
    const int hb = blockIdx.y;
    const int b = hb & 1;
    const int qBase = blockIdx.x * 128;

    const __half* __restrict__ Q = g_qh + (size_t)hb * SLQ * DH;
    const __half* __restrict__ K = g_kh + (size_t)hb * SLK * DH;
    const __half* __restrict__ V = g_vh + (size_t)hb * SLK * DH;
    __half* __restrict__ O = g_oh + (size_t)hb * SLQ * DH;

    const int r0 = qBase + warp * 16 + g;
    const int r1 = r0 + 8;

    // Q fragments straight from global (packed half2)
    unsigned qf[4][4];
    #pragma unroll
    for (int ks = 0; ks < 4; ks++) {
        qf[ks][0] = *(const unsigned*)&Q[(size_t)r0 * DH + ks * 16 + 2 * tq];
        qf[ks][1] = *(const unsigned*)&Q[(size_t)r1 * DH + ks * 16 + 2 * tq];
        qf[ks][2] = *(const unsigned*)&Q[(size_t)r0 * DH + ks * 16 + 8 + 2 * tq];
        qf[ks][3] = *(const unsigned*)&Q[(size_t)r1 * DH + ks * 16 + 8 + 2 * tq];
    }

    const int i8 = lane & 7, sel = lane >> 3;
    const int rowK = ((sel >> 1) << 3) + i8;   // K: non-trans tiles
    const int colK = (sel & 1) << 3;
    const int rowV = ((sel & 1) << 3) + i8;    // V: trans tiles
    const int colV = (sel >> 1) << 3;
    const unsigned kSm = (unsigned)__cvta_generic_to_shared(&Ks[0][0][0]);
    const unsigned vSm = (unsigned)__cvta_generic_to_shared(&Vs[0][0][0]);
    const unsigned kAddr0 = kSm + (rowK * 72 + colK) * 2;
    const unsigned vAddr0 = vSm + (rowV * 72 + colV) * 2;
    const unsigned BUFB = 64 * 72 * 2;

    float oc[8][4];
    #pragma unroll
    for (int dt = 0; dt < 8; dt++)
        #pragma unroll
        for (int i = 0; i < 4; i++) oc[dt][i] = 0.f;
    float m0 = -1e30f, m1 = -1e30f, l0 = 0.f, l1 = 0.f;

    const float scale = 0.125f;
    const unsigned* mb0 = &g_mbits[((size_t)(b << 11) + r0) * 64];
    const unsigned* mb1 = &g_mbits[((size_t)(b << 11) + r1) * 64];

    const int srow = t >> 3, sseg = (t & 7) * 8;

    auto stage = [&](int kb, int buf) {
        #pragma unroll
        for (int it = 0; it < 2; it++) {
            int row = srow + it * 32;
            cp16(kSm + ((buf * 64 + row) * 72 + sseg) * 2,
                 &K[(size_t)(kb + row) * DH + sseg]);
            cp16(vSm + ((buf * 64 + row) * 72 + sseg) * 2,
                 &V[(size_t)(kb + row) * DH + sseg]);
        }
        cp_commit();
    };

    stage(0, 0);
    const int NT = SLK / 64;  // 32
    for (int it = 0; it < NT; it++) {
        cp_wait0();
        __syncthreads();
        if (it + 1 < NT) stage((it + 1) * 64, (it + 1) & 1);
        const unsigned kA = kAddr0 + (it & 1) * BUFB;
        const unsigned vA = vAddr0 + (it & 1) * BUFB;
        const int kb = it * 64;

        // S = Q K^T  (m16 x n64 per warp)
        float sc[8][4];
        #pragma unroll
        for (int nt = 0; nt < 8; nt++)
            #pragma unroll
            for (int i = 0; i < 4; i++) sc[nt][i] = 0.f;

        #pragma unroll
        for (int ks = 0; ks < 4; ks++) {
            #pragma unroll
            for (int ntp = 0; ntp < 4; ntp++) {
                unsigned b0, b1, b2, b3;
                ldsm4(b0, b1, b2, b3, kA + (ntp * 16 * 72 + ks * 16) * 2);
                mma16816(sc[ntp * 2],     qf[ks][0], qf[ks][1], qf[ks][2], qf[ks][3], b0, b1);
                mma16816(sc[ntp * 2 + 1], qf[ks][0], qf[ks][1], qf[ks][2], qf[ks][3], b2, b3);
            }
        }

        // mask + scale
        uint2 w0 = *(const uint2*)&mb0[kb >> 5];
        uint2 w1 = *(const uint2*)&mb1[kb >> 5];
        unsigned long long mm0 = (unsigned long long)w0.x | ((unsigned long long)w0.y << 32);
        unsigned long long mm1 = (unsigned long long)w1.x | ((unsigned long long)w1.y << 32);
        #pragma unroll
        for (int nt = 0; nt < 8; nt++) {
            int c0 = nt * 8 + tq * 2, c1 = c0 + 1;
            sc[nt][0] = ((mm0 >> c0) & 1ULL) ? -1e30f : sc[nt][0] * scale;
            sc[nt][1] = ((mm0 >> c1) & 1ULL) ? -1e30f : sc[nt][1] * scale;
            sc[nt][2] = ((mm1 >> c0) & 1ULL) ? -1e30f : sc[nt][2] * scale;
            sc[nt][3] = ((mm1 >> c1) & 1ULL) ? -1e30f : sc[nt][3] * scale;
        }

        // online softmax (quad-pair reduction)
        float mx0 = -1e30f, mx1 = -1e30f;
        #pragma unroll
        for (int nt = 0; nt < 8; nt++) {
            mx0 = fmaxf(mx0, fmaxf(sc[nt][0], sc[nt][1]));
            mx1 = fmaxf(mx1, fmaxf(sc[nt][2], sc[nt][3]));
        }
        mx0 = fmaxf(mx0, __shfl_xor_sync(0xffffffffu, mx0, 1));
        mx0 = fmaxf(mx0, __shfl_xor_sync(0xffffffffu, mx0, 2));
        mx1 = fmaxf(mx1, __shfl_xor_sync(0xffffffffu, mx1, 1));
        mx1 = fmaxf(mx1, __shfl_xor_sync(0xffffffffu, mx1, 2));

        float newm0 = fmaxf(m0, mx0), newm1 = fmaxf(m1, mx1);
        float al0 = __expf(m0 - newm0), al1 = __expf(m1 - newm1);
        m0 = newm0; m1 = newm1;

        float rs0 = 0.f, rs1 = 0.f;
        #pragma unroll
        for (int nt = 0; nt < 8; nt++) {
            sc[nt][0] = __expf(sc[nt][0] - newm0);
            sc[nt][1] = __expf(sc[nt][1] - newm0);
            sc[nt][2] = __expf(sc[nt][2] - newm1);
            sc[nt][3] = __expf(sc[nt][3] - newm1);
            rs0 += sc[nt][0] + sc[nt][1];
            rs1 += sc[nt][2] + sc[nt][3];
        }
        rs0 += __shfl_xor_sync(0xffffffffu, rs0, 1);
        rs0 += __shfl_xor_sync(0xffffffffu, rs0, 2);
        rs1 += __shfl_xor_sync(0xffffffffu, rs1, 1);
        rs1 += __shfl_xor_sync(0xffffffffu, rs1, 2);
        l0 = l0 * al0 + rs0;
        l1 = l1 * al1 + rs1;

        #pragma unroll
        for (int dt = 0; dt < 8; dt++) {
            oc[dt][0] *= al0; oc[dt][1] *= al0;
            oc[dt][2] *= al1; oc[dt][3] *= al1;
        }

        // pack P into fp16 A fragments (layouts coincide)
        unsigned pf[8][2];
        #pragma unroll
        for (int nt = 0; nt < 8; nt++) {
            pf[nt][0] = pack2(sc[nt][0], sc[nt][1]);
            pf[nt][1] = pack2(sc[nt][2], sc[nt][3]);
        }

        // O += P V
        #pragma unroll
        for (int ks = 0; ks < 4; ks++) {
            unsigned a0 = pf[2 * ks][0], a1 = pf[2 * ks][1];
            unsigned a2 = pf[2 * ks + 1][0], a3 = pf[2 * ks + 1][1];
            #pragma unroll
            for (int dtp = 0; dtp < 4; dtp++) {
                unsigned b0, b1, b2, b3;
                ldsm4t(b0, b1, b2, b3, vA + (ks * 16 * 72 + dtp * 16) * 2);
                mma16816(oc[dtp * 2],     a0, a1, a2, a3, b0, b1);
                mma16816(oc[dtp * 2 + 1], a0, a1, a2, a3, b2, b3);
            }
        }
    }

    // epilogue (half)
    float inv0 = 1.f / l0, inv1 = 1.f / l1;
    #pragma unroll
    for (int dt = 0; dt < 8; dt++) {
        int d = dt * 8 + tq * 2;
        *(unsigned*)&O[(size_t)r0 * DH + d] = pack2(oc[dt][0] * inv0, oc[dt][1] * inv0);
        *(unsigned*)&O[(size_t)r1 * DH + d] = pack2(oc[dt][2] * inv1, oc[dt][3] * inv1);
    }
}

// ---------------------------------------------------------------------------
// LayerNorm (ddof=1, eps on std)
// ---------------------------------------------------------------------------
__global__ __launch_bounds__(256) void ln_kernel(
    const float* __restrict__ gamma, const float* __restrict__ beta,
    float* __restrict__ out)
{
    __shared__ float red[8];
    const int row = blockIdx.x;
    const int t = threadIdx.x;
    const float* x = g_x + (size_t)row * DM;

    float4 v = *(const float4*)&x[t * 4];
    float s = v.x + v.y + v.z + v.w;
    #pragma unroll
    for (int sft = 16; sft >= 1; sft >>= 1)
        s += __shfl_xor_sync(0xffffffffu, s, sft);
    if ((t & 31) == 0) red[t >> 5] = s;
    __syncthreads();
    float tot = 0.f;
    #pragma unroll
    for (int w = 0; w < 8; w++) tot += red[w];
    float mean = tot * (1.0f / DM);
    __syncthreads();

    float d0 = v.x - mean, d1 = v.y - mean, d2 = v.z - mean, d3 = v.w - mean;
    float sq = d0 * d0 + d1 * d1 + d2 * d2 + d3 * d3;
    #pragma unroll
    for (int sft = 16; sft >= 1; sft >>= 1)
        sq += __shfl_xor_sync(0xffffffffu, sq, sft);
    if ((t & 31) == 0) red[t >> 5] = sq;
    __syncthreads();
    float sqt = 0.f;
    #pragma unroll
    for (int w = 0; w < 8; w++) sqt += red[w];
    float stdv = sqrtf(sqt * (1.0f / (DM - 1)));
    float inv = 1.0f / (stdv + 1e-3f);

    float4 gm = *(const float4*)&gamma[t * 4];
    float4 be = *(const float4*)&beta[t * 4];
    float4 o;
    o.x = d0 * inv * gm.x + be.x;
    o.y = d1 * inv * gm.y + be.y;
    o.z = d2 * inv * gm.z + be.z;
    o.w = d3 * inv * gm.w + be.w;
    *(float4*)&out[(size_t)row * DM + t * 4] = o;
}

// ---------------------------------------------------------------------------
extern "C" void kernel_launch(void* const* d_in, const int* in_sizes, int n_in,
                              void* d_out, int out_size)
{
    const float* v_in  = (const float*)d_in[0];
    const float* k_in  = (const float*)d_in[1];
    const float* q_in  = (const float*)d_in[2];
    const void*  mask  = d_in[3];
    const float* w_q   = (const float*)d_in[4];
    const float* w_k   = (const float*)d_in[5];
    const float* w_v   = (const float*)d_in[6];
    const float* w_o   = (const float*)d_in[7];
    const float* b_o   = (const float*)d_in[8];
    const float* gamma = (const float*)d_in[9];
    const float* beta  = (const float*)d_in[10];
    float* out = (float*)d_out;

    cudaFuncSetAttribute(proj_kernel, cudaFuncAttributeMaxDynamicSharedMemorySize, GEMM_SMEM);
    cudaFuncSetAttribute(outproj_kernel, cudaFuncAttributeMaxDynamicSharedMemorySize, GEMM_SMEM);

    sniff_mask_kernel<<<1, 256>>>((const unsigned int*)mask, 16384);
    pack_mask_kernel<<<2048, 256>>>(mask);
    f2h_all_kernel<<<dim3(256, 7), 256>>>(q_in, k_in, v_in, w_q, w_k, w_v, w_o);

    proj_kernel<<<dim3(NH / 2, MROWS / 128, 3), 256, GEMM_SMEM>>>();
    attn_kernel<<<dim3(SLQ / 128, NH * BB), 256>>>();
    outproj_kernel<<<dim3(DM / 128, MROWS / 128), 256, GEMM_SMEM>>>(k_in, b_o);
    ln_kernel<<<MROWS, 256>>>(gamma, beta, out);
}

// round 7
// speedup vs baseline: 6.1443x; 1.0414x over previous
#include <cuda_runtime.h>
#include <cuda_fp16.h>
#include <cstdint>

#define BB 2
#define SLQ 2048
#define SLK 2048
#define DM 1024
#define NH 16
#define DH 64
#define MROWS (BB*SLQ)   // 4096

// Scratch (allocation-free rule: device globals)
__device__ __half g_qh[NH*BB*SLQ*DH];
__device__ __half g_kh[NH*BB*SLK*DH];
__device__ __half g_vh[NH*BB*SLK*DH];
__device__ __half g_oh[NH*BB*SLQ*DH];
__device__ __half g_xq[MROWS*DM];
__device__ __half g_xk[MROWS*DM];
__device__ __half g_xv[MROWS*DM];
__device__ __half g_wq[NH*DM*DH];
__device__ __half g_wk[NH*DM*DH];
__device__ __half g_wv[NH*DM*DH];
__device__ __half g_wo[DM*DM];
__device__ float  g_x [MROWS*DM];
__device__ unsigned int g_mbits[BB*SLQ*(SLK/32)];
__device__ int g_mask_is_u8;

// ---------------------------------------------------------------------------
__device__ __forceinline__ unsigned pack2(float a, float b) {
    __half2 h = __floats2half2_rn(a, b);
    return *(unsigned*)&h;
}

__device__ __forceinline__ unsigned ex2h2(unsigned x) {
    unsigned r;
    asm("ex2.approx.f16x2 %0, %1;" : "=r"(r) : "r"(x));
    return r;
}

__device__ __forceinline__ float ex2f(float x) {
    float r;
    asm("ex2.approx.f32 %0, %1;" : "=f"(r) : "f"(x));
    return r;
}

__device__ __forceinline__ void mma16816(float* c,
    unsigned a0, unsigned a1, unsigned a2, unsigned a3,
    unsigned b0, unsigned b1)
{
    asm volatile(
        "mma.sync.aligned.m16n8k16.row.col.f32.f16.f16.f32 "
        "{%0,%1,%2,%3}, {%4,%5,%6,%7}, {%8,%9}, {%0,%1,%2,%3};"
        : "+f"(c[0]), "+f"(c[1]), "+f"(c[2]), "+f"(c[3])
        : "r"(a0), "r"(a1), "r"(a2), "r"(a3), "r"(b0), "r"(b1));
}

__device__ __forceinline__ void ldsm4(unsigned& r0, unsigned& r1,
                                      unsigned& r2, unsigned& r3, unsigned addr)
{
    asm volatile("ldmatrix.sync.aligned.m8n8.x4.shared.b16 {%0,%1,%2,%3}, [%4];"
        : "=r"(r0), "=r"(r1), "=r"(r2), "=r"(r3) : "r"(addr));
}

__device__ __forceinline__ void ldsm4t(unsigned& r0, unsigned& r1,
                                       unsigned& r2, unsigned& r3, unsigned addr)
{
    asm volatile("ldmatrix.sync.aligned.m8n8.x4.trans.shared.b16 {%0,%1,%2,%3}, [%4];"
        : "=r"(r0), "=r"(r1), "=r"(r2), "=r"(r3) : "r"(addr));
}

__device__ __forceinline__ void cp16(unsigned smem, const void* gptr)
{
    asm volatile("cp.async.cg.shared.global [%0], [%1], 16;" :: "r"(smem), "l"(gptr));
}
__device__ __forceinline__ void cp_commit() { asm volatile("cp.async.commit_group;"); }
__device__ __forceinline__ void cp_wait0()  { asm volatile("cp.async.wait_group 0;"); }

// ---------------------------------------------------------------------------
__global__ void sniff_mask_kernel(const unsigned int* __restrict__ mw, int nwords)
{
    __shared__ int found;
    if (threadIdx.x == 0) found = 0;
    __syncthreads();
    for (int i = threadIdx.x; i < nwords; i += blockDim.x)
        if (mw[i] > 1u) { found = 1; break; }
    __syncthreads();
    if (threadIdx.x == 0) g_mask_is_u8 = found;
}

__global__ void pack_mask_kernel(const void* __restrict__ mraw)
{
    const int nwords = BB * SLQ * (SLK / 32);
    const int lane = threadIdx.x & 31;
    int gw = (blockIdx.x * blockDim.x + threadIdx.x) >> 5;
    const int stride = (gridDim.x * blockDim.x) >> 5;
    const bool u8 = (g_mask_is_u8 != 0);
    for (int w = gw; w < nwords; w += stride) {
        int idx = w * 32 + lane;
        int v = u8 ? (int)((const unsigned char*)mraw)[idx]
                   : ((const int*)mraw)[idx];
        unsigned int bits = __ballot_sync(0xffffffffu, v != 0);
        if (lane == 0) g_mbits[w] = bits;
    }
}

// Fused fp32 -> fp16 prepack for all 7 tensors. grid.y = region.
__global__ void f2h_all_kernel(
    const float* __restrict__ s0, const float* __restrict__ s1,
    const float* __restrict__ s2, const float* __restrict__ s3,
    const float* __restrict__ s4, const float* __restrict__ s5,
    const float* __restrict__ s6)
{
    const float* src;
    __half* dst;
    int n;
    switch (blockIdx.y) {
        case 0: src = s0; dst = g_xq; n = MROWS * DM; break;
        case 1: src = s1; dst = g_xk; n = MROWS * DM; break;
        case 2: src = s2; dst = g_xv; n = MROWS * DM; break;
        case 3: src = s3; dst = g_wq; n = NH * DM * DH; break;
        case 4: src = s4; dst = g_wk; n = NH * DM * DH; break;
        case 5: src = s5; dst = g_wv; n = NH * DM * DH; break;
        default: src = s6; dst = g_wo; n = DM * DM; break;
    }
    int i = (blockIdx.x * blockDim.x + threadIdx.x) * 4;
    int stride = gridDim.x * blockDim.x * 4;
    for (; i < n; i += stride) {
        float4 v = *(const float4*)&src[i];
        *(uint2*)&dst[i] = make_uint2(pack2(v.x, v.y), pack2(v.z, v.w));
    }
}

// ---------------------------------------------------------------------------
// Projection GEMM (fp16 mma): C[h,b,l,e] = sum_d X[b,l,d]*W[h,d,e]
// Block 128(M) x 128(N = 2 heads), k-tile 64, cp.async double buffered.
// ---------------------------------------------------------------------------
#define ASZ (128*72)
#define BSZ (64*136)
#define GEMM_SMEM ((2*ASZ + 2*BSZ) * 2)

__global__ __launch_bounds__(256, 2) void proj_kernel()
{
    extern __shared__ __half dsm[];
    __half* Asm = dsm;
    __half* Bsm = dsm + 2 * ASZ;

    const __half* __restrict__ X;
    const __half* __restrict__ W;
    __half* __restrict__ C;
    if (blockIdx.z == 0)      { X = g_xq; W = g_wq; C = g_qh; }
    else if (blockIdx.z == 1) { X = g_xk; W = g_wk; C = g_kh; }
    else                      { X = g_xv; W = g_wv; C = g_vh; }

    const int t = threadIdx.x;
    const int warp = t >> 5, lane = t & 31;
    const int g = lane >> 2, tq = lane & 3;
    const int wm = warp >> 2, wn = warp & 3;
    const int mBase = blockIdx.y * 128;
    const int h0 = blockIdx.x * 2;

    const int i8 = lane & 7, sel = lane >> 3;
    const int rowF = ((sel & 1) << 3) + i8;
    const int colF = (sel >> 1) << 3;
    const unsigned aSm = (unsigned)__cvta_generic_to_shared(Asm);
    const unsigned bSm = (unsigned)__cvta_generic_to_shared(Bsm);

    float acc[4][4][4];
    #pragma unroll
    for (int mt = 0; mt < 4; mt++)
        #pragma unroll
        for (int nt = 0; nt < 4; nt++)
            #pragma unroll
            for (int i = 0; i < 4; i++) acc[mt][nt][i] = 0.f;

    const int arow = t >> 3, aseg = (t & 7) * 8;
    const int brow = t >> 4, bseg = (t & 15) * 8;

    auto stage = [&](int kt, int buf) {
        #pragma unroll
        for (int it = 0; it < 4; it++) {
            int row = arow + it * 32;
            cp16(aSm + ((buf * 128 + row) * 72 + aseg) * 2,
                 &X[(size_t)(mBase + row) * DM + kt + aseg]);
        }
        #pragma unroll
        for (int it = 0; it < 4; it++) {
            int row = brow + it * 16;
            int head = h0 + (bseg >> 6), e = bseg & 63;
            cp16(bSm + ((buf * 64 + row) * 136 + bseg) * 2,
                 &W[((size_t)head * DM + kt + row) * DH + e]);
        }
        cp_commit();
    };

    stage(0, 0);
    const int NKT = DM / 64;  // 16
    for (int it = 0; it < NKT; it++) {
        cp_wait0();
        __syncthreads();
        if (it + 1 < NKT) stage((it + 1) * 64, (it + 1) & 1);
        const int abuf = (it & 1) * 128, bbuf = (it & 1) * 64;

        #pragma unroll
        for (int ks = 0; ks < 4; ks++) {
            unsigned af[4][4];
            #pragma unroll
            for (int mt = 0; mt < 4; mt++)
                ldsm4(af[mt][0], af[mt][1], af[mt][2], af[mt][3],
                      aSm + ((abuf + wm * 64 + mt * 16 + rowF) * 72 + ks * 16 + colF) * 2);
            #pragma unroll
            for (int ntp = 0; ntp < 2; ntp++) {
                unsigned b0, b1, b2, b3;
                ldsm4t(b0, b1, b2, b3,
                       bSm + ((bbuf + ks * 16 + rowF) * 136 + wn * 32 + ntp * 16 + colF) * 2);
                #pragma unroll
                for (int mt = 0; mt < 4; mt++) {
                    mma16816(acc[mt][ntp * 2],     af[mt][0], af[mt][1], af[mt][2], af[mt][3], b0, b1);
                    mma16816(acc[mt][ntp * 2 + 1], af[mt][0], af[mt][1], af[mt][2], af[mt][3], b2, b3);
                }
            }
        }
    }

    #pragma unroll
    for (int mt = 0; mt < 4; mt++) {
        int r0 = mBase + wm * 64 + mt * 16 + g;
        int r1 = r0 + 8;
        int b0i = r0 >> 11, l0 = r0 & 2047;
        int b1i = r1 >> 11, l1 = r1 & 2047;
        #pragma unroll
        for (int nt = 0; nt < 4; nt++) {
            int n = wn * 32 + nt * 8 + tq * 2;
            int head = h0 + (n >> 6), e = n & 63;
            __half* c0 = C + (((size_t)(head * BB + b0i) << 11) + l0) * DH;
            __half* c1 = C + (((size_t)(head * BB + b1i) << 11) + l1) * DH;
            *(unsigned*)&c0[e] = pack2(acc[mt][nt][0], acc[mt][nt][1]);
            *(unsigned*)&c1[e] = pack2(acc[mt][nt][2], acc[mt][nt][3]);
        }
    }
}

// ---------------------------------------------------------------------------
// Output projection: g_x = Ocat @ Wo + bo + resid (fp32 out)
// ---------------------------------------------------------------------------
__global__ __launch_bounds__(256, 2) void outproj_kernel(
    const float* __restrict__ resid, const float* __restrict__ bo)
{
    extern __shared__ __half dsm[];
    __half* Asm = dsm;
    __half* Bsm = dsm + 2 * ASZ;

    const int t = threadIdx.x;
    const int warp = t >> 5, lane = t & 31;
    const int g = lane >> 2, tq = lane & 3;
    const int wm = warp >> 2, wn = warp & 3;
    const int mBase = blockIdx.y * 128;
    const int nBase = blockIdx.x * 128;

    const int i8 = lane & 7, sel = lane >> 3;
    const int rowF = ((sel & 1) << 3) + i8;
    const int colF = (sel >> 1) << 3;
    const unsigned aSm = (unsigned)__cvta_generic_to_shared(Asm);
    const unsigned bSm = (unsigned)__cvta_generic_to_shared(Bsm);

    float acc[4][4][4];
    #pragma unroll
    for (int mt = 0; mt < 4; mt++)
        #pragma unroll
        for (int nt = 0; nt < 4; nt++)
            #pragma unroll
            for (int i = 0; i < 4; i++) acc[mt][nt][i] = 0.f;

    const int arow = t >> 3, aseg = (t & 7) * 8;
    const int brow = t >> 4, bseg = (t & 15) * 8;

    auto stage = [&](int kt, int buf) {
        const int kh = kt >> 6;
        #pragma unroll
        for (int it = 0; it < 4; it++) {
            int row = arow + it * 32;
            int m = mBase + row;
            int mb = m >> 11, ml = m & 2047;
            cp16(aSm + ((buf * 128 + row) * 72 + aseg) * 2,
                 &g_oh[(((size_t)(kh * BB + mb) << 11) + ml) * DH + aseg]);
        }
        #pragma unroll
        for (int it = 0; it < 4; it++) {
            int row = brow + it * 16;
            cp16(bSm + ((buf * 64 + row) * 136 + bseg) * 2,
                 &g_wo[(size_t)(kt + row) * DM + nBase + bseg]);
        }
        cp_commit();
    };

    stage(0, 0);
    const int NKT = DM / 64;
    for (int it = 0; it < NKT; it++) {
        cp_wait0();
        __syncthreads();
        if (it + 1 < NKT) stage((it + 1) * 64, (it + 1) & 1);
        const int abuf = (it & 1) * 128, bbuf = (it & 1) * 64;

        #pragma unroll
        for (int ks = 0; ks < 4; ks++) {
            unsigned af[4][4];
            #pragma unroll
            for (int mt = 0; mt < 4; mt++)
                ldsm4(af[mt][0], af[mt][1], af[mt][2], af[mt][3],
                      aSm + ((abuf + wm * 64 + mt * 16 + rowF) * 72 + ks * 16 + colF) * 2);
            #pragma unroll
            for (int ntp = 0; ntp < 2; ntp++) {
                unsigned b0, b1, b2, b3;
                ldsm4t(b0, b1, b2, b3,
                       bSm + ((bbuf + ks * 16 + rowF) * 136 + wn * 32 + ntp * 16 + colF) * 2);
                #pragma unroll
                for (int mt = 0; mt < 4; mt++) {
                    mma16816(acc[mt][ntp * 2],     af[mt][0], af[mt][1], af[mt][2], af[mt][3], b0, b1);
                    mma16816(acc[mt][ntp * 2 + 1], af[mt][0], af[mt][1], af[mt][2], af[mt][3], b2, b3);
                }
            }
        }
    }

    #pragma unroll
    for (int mt = 0; mt < 4; mt++) {
        int r0 = mBase + wm * 64 + mt * 16 + g;
        int r1 = r0 + 8;
        #pragma unroll
        for (int nt = 0; nt < 4; nt++) {
            int n = nBase + wn * 32 + nt * 8 + tq * 2;
            float2 bb = *(const float2*)&bo[n];
            float2 rA = *(const float2*)&resid[(size_t)r0 * DM + n];
            float2 rB = *(const float2*)&resid[(size_t)r1 * DM + n];
            *(float2*)&g_x[(size_t)r0 * DM + n] =
                make_float2(acc[mt][nt][0] + bb.x + rA.x, acc[mt][nt][1] + bb.y + rA.y);
            *(float2*)&g_x[(size_t)r1 * DM + n] =
                make_float2(acc[mt][nt][2] + bb.x + rB.x, acc[mt][nt][3] + bb.y + rB.y);
        }
    }
}

// ---------------------------------------------------------------------------
// Flash attention (fp16 mma, cp.async, f16x2 exp2 softmax).
// ---------------------------------------------------------------------------
__global__ __launch_bounds__(256, 2) void attn_kernel()
{
    __shared__ __half Ks[2][64][72];
    __shared__ __half Vs[2][64][72];

    const int t = threadIdx.x;
    const int warp = t >> 5, lane = t & 31;
    const int g = lane >> 2, tq = lane & 3;
    const int hb = blockIdx.y;
    const int b = hb & 1;
    const int qBase = blockIdx.x * 128;

    const __half* __restrict__ Q = g_qh + (size_t)hb * SLQ * DH;
    const __half* __restrict__ K = g_kh + (size_t)hb * SLK * DH;
    const __half* __restrict__ V = g_vh + (size_t)hb * SLK * DH;
    __half* __restrict__ O = g_oh + (size_t)hb * SLQ * DH;

    const int r0 = qBase + warp * 16 + g;
    const int r1 = r0 + 8;

    unsigned qf[4][4];
    #pragma unroll
    for (int ks = 0; ks < 4; ks++) {
        qf[ks][0] = *(const unsigned*)&Q[(size_t)r0 * DH + ks * 16 + 2 * tq];
        qf[ks][1] = *(const unsigned*)&Q[(size_t)r1 * DH + ks * 16 + 2 * tq];
        qf[ks][2] = *(const unsigned*)&Q[(size_t)r0 * DH + ks * 16 + 8 + 2 * tq];
        qf[ks][3] = *(const unsigned*)&Q[(size_t)r1 * DH + ks * 16 + 8 + 2 * tq];
    }

    const int i8 = lane & 7, sel = lane >> 3;
    const int rowK = ((sel >> 1) << 3) + i8;
    const int colK = (sel & 1) << 3;
    const int rowV = ((sel & 1) << 3) + i8;
    const int colV = (sel >> 1) << 3;
    const unsigned kSm = (unsigned)__cvta_generic_to_shared(&Ks[0][0][0]);
    const unsigned vSm = (unsigned)__cvta_generic_to_shared(&Vs[0][0][0]);
    const unsigned kAddr0 = kSm + (rowK * 72 + colK) * 2;
    const unsigned vAddr0 = vSm + (rowV * 72 + colV) * 2;
    const unsigned BUFB = 64 * 72 * 2;

    float oc[8][4];
    #pragma unroll
    for (int dt = 0; dt < 8; dt++)
        #pragma unroll
        for (int i = 0; i < 4; i++) oc[dt][i] = 0.f;
    float m0 = -1e30f, m1 = -1e30f, l0 = 0.f, l1 = 0.f;

    // log2-domain scale: 1/sqrt(64) * log2(e)
    const float c = 0.18033688011112042f;
    const unsigned* mb0 = &g_mbits[((size_t)(b << 11) + r0) * 64];
    const unsigned* mb1 = &g_mbits[((size_t)(b << 11) + r1) * 64];

    const int srow = t >> 3, sseg = (t & 7) * 8;

    auto stage = [&](int kb, int buf) {
        #pragma unroll
        for (int it = 0; it < 2; it++) {
            int row = srow + it * 32;
            cp16(kSm + ((buf * 64 + row) * 72 + sseg) * 2,
                 &K[(size_t)(kb + row) * DH + sseg]);
            cp16(vSm + ((buf * 64 + row) * 72 + sseg) * 2,
                 &V[(size_t)(kb + row) * DH + sseg]);
        }
        cp_commit();
    };

    stage(0, 0);
    const int NT = SLK / 64;  // 32
    for (int it = 0; it < NT; it++) {
        cp_wait0();
        __syncthreads();
        if (it + 1 < NT) stage((it + 1) * 64, (it + 1) & 1);
        const unsigned kA = kAddr0 + (it & 1) * BUFB;
        const unsigned vA = vAddr0 + (it & 1) * BUFB;
        const int kb = it * 64;

        // S = Q K^T
        float sc[8][4];
        #pragma unroll
        for (int nt = 0; nt < 8; nt++)
            #pragma unroll
            for (int i = 0; i < 4; i++) sc[nt][i] = 0.f;

        #pragma unroll
        for (int ks = 0; ks < 4; ks++) {
            #pragma unroll
            for (int ntp = 0; ntp < 4; ntp++) {
                unsigned b0, b1, b2, b3;
                ldsm4(b0, b1, b2, b3, kA + (ntp * 16 * 72 + ks * 16) * 2);
                mma16816(sc[ntp * 2],     qf[ks][0], qf[ks][1], qf[ks][2], qf[ks][3], b0, b1);
                mma16816(sc[ntp * 2 + 1], qf[ks][0], qf[ks][1], qf[ks][2], qf[ks][3], b2, b3);
            }
        }

        // mask + scale into log2 domain
        uint2 w0 = *(const uint2*)&mb0[kb >> 5];
        uint2 w1 = *(const uint2*)&mb1[kb >> 5];
        unsigned long long mm0 = (unsigned long long)w0.x | ((unsigned long long)w0.y << 32);
        unsigned long long mm1 = (unsigned long long)w1.x | ((unsigned long long)w1.y << 32);
        #pragma unroll
        for (int nt = 0; nt < 8; nt++) {
            int c0 = nt * 8 + tq * 2, c1 = c0 + 1;
            sc[nt][0] = ((mm0 >> c0) & 1ULL) ? -1e30f : sc[nt][0] * c;
            sc[nt][1] = ((mm0 >> c1) & 1ULL) ? -1e30f : sc[nt][1] * c;
            sc[nt][2] = ((mm1 >> c0) & 1ULL) ? -1e30f : sc[nt][2] * c;
            sc[nt][3] = ((mm1 >> c1) & 1ULL) ? -1e30f : sc[nt][3] * c;
        }

        // row max (quad reduction: lanes xor 1,2 share rows)
        float mx0 = -1e30f, mx1 = -1e30f;
        #pragma unroll
        for (int nt = 0; nt < 8; nt++) {
            mx0 = fmaxf(mx0, fmaxf(sc[nt][0], sc[nt][1]));
            mx1 = fmaxf(mx1, fmaxf(sc[nt][2], sc[nt][3]));
        }
        mx0 = fmaxf(mx0, __shfl_xor_sync(0xffffffffu, mx0, 1));
        mx0 = fmaxf(mx0, __shfl_xor_sync(0xffffffffu, mx0, 2));
        mx1 = fmaxf(mx1, __shfl_xor_sync(0xffffffffu, mx1, 1));
        mx1 = fmaxf(mx1, __shfl_xor_sync(0xffffffffu, mx1, 2));

        float newm0 = fmaxf(m0, mx0), newm1 = fmaxf(m1, mx1);
        float al0 = ex2f(m0 - newm0), al1 = ex2f(m1 - newm1);
        m0 = newm0; m1 = newm1;

        // p = 2^(s - m) via f16x2 MUFU; output IS the fp16 A-fragment
        unsigned pf[8][2];
        __half2 hs0 = __floats2half2_rn(0.f, 0.f);
        __half2 hs1 = hs0;
        #pragma unroll
        for (int nt = 0; nt < 8; nt++) {
            pf[nt][0] = ex2h2(pack2(sc[nt][0] - newm0, sc[nt][1] - newm0));
            pf[nt][1] = ex2h2(pack2(sc[nt][2] - newm1, sc[nt][3] - newm1));
            hs0 = __hadd2(hs0, *(__half2*)&pf[nt][0]);
            hs1 = __hadd2(hs1, *(__half2*)&pf[nt][1]);
        }
        float2 f0 = __half22float2(hs0);
        float2 f1 = __half22float2(hs1);
        float rs0 = f0.x + f0.y, rs1 = f1.x + f1.y;
        rs0 += __shfl_xor_sync(0xffffffffu, rs0, 1);
        rs0 += __shfl_xor_sync(0xffffffffu, rs0, 2);
        rs1 += __shfl_xor_sync(0xffffffffu, rs1, 1);
        rs1 += __shfl_xor_sync(0xffffffffu, rs1, 2);
        l0 = l0 * al0 + rs0;
        l1 = l1 * al1 + rs1;

        #pragma unroll
        for (int dt = 0; dt < 8; dt++) {
            oc[dt][0] *= al0; oc[dt][1] *= al0;
            oc[dt][2] *= al1; oc[dt][3] *= al1;
        }

        // O += P V
        #pragma unroll
        for (int ks = 0; ks < 4; ks++) {
            unsigned a0 = pf[2 * ks][0], a1 = pf[2 * ks][1];
            unsigned a2 = pf[2 * ks + 1][0], a3 = pf[2 * ks + 1][1];
            #pragma unroll
            for (int dtp = 0; dtp < 4; dtp++) {
                unsigned b0, b1, b2, b3;
                ldsm4t(b0, b1, b2, b3, vA + (ks * 16 * 72 + dtp * 16) * 2);
                mma16816(oc[dtp * 2],     a0, a1, a2, a3, b0, b1);
                mma16816(oc[dtp * 2 + 1], a0, a1, a2, a3, b2, b3);
            }
        }
    }

    float inv0 = 1.f / l0, inv1 = 1.f / l1;
    #pragma unroll
    for (int dt = 0; dt < 8; dt++) {
        int d = dt * 8 + tq * 2;
        *(unsigned*)&O[(size_t)r0 * DH + d] = pack2(oc[dt][0] * inv0, oc[dt][1] * inv0);
        *(unsigned*)&O[(size_t)r1 * DH + d] = pack2(oc[dt][2] * inv1, oc[dt][3] * inv1);
    }
}

// ---------------------------------------------------------------------------
// LayerNorm (ddof=1, eps on std)
// ---------------------------------------------------------------------------
__global__ __launch_bounds__(256) void ln_kernel(
    const float* __restrict__ gamma, const float* __restrict__ beta,
    float* __restrict__ out)
{
    __shared__ float red[8];
    const int row = blockIdx.x;
    const int t = threadIdx.x;
    const float* x = g_x + (size_t)row * DM;

    float4 v = *(const float4*)&x[t * 4];
    float s = v.x + v.y + v.z + v.w;
    #pragma unroll
    for (int sft = 16; sft >= 1; sft >>= 1)
        s += __shfl_xor_sync(0xffffffffu, s, sft);
    if ((t & 31) == 0) red[t >> 5] = s;
    __syncthreads();
    float tot = 0.f;
    #pragma unroll
    for (int w = 0; w < 8; w++) tot += red[w];
    float mean = tot * (1.0f / DM);
    __syncthreads();

    float d0 = v.x - mean, d1 = v.y - mean, d2 = v.z - mean, d3 = v.w - mean;
    float sq = d0 * d0 + d1 * d1 + d2 * d2 + d3 * d3;
    #pragma unroll
    for (int sft = 16; sft >= 1; sft >>= 1)
        sq += __shfl_xor_sync(0xffffffffu, sq, sft);
    if ((t & 31) == 0) red[t >> 5] = sq;
    __syncthreads();
    float sqt = 0.f;
    #pragma unroll
    for (int w = 0; w < 8; w++) sqt += red[w];
    float stdv = sqrtf(sqt * (1.0f / (DM - 1)));
    float inv = 1.0f / (stdv + 1e-3f);

    float4 gm = *(const float4*)&gamma[t * 4];
    float4 be = *(const float4*)&beta[t * 4];
    float4 o;
    o.x = d0 * inv * gm.x + be.x;
    o.y = d1 * inv * gm.y + be.y;
    o.z = d2 * inv * gm.z + be.z;
    o.w = d3 * inv * gm.w + be.w;
    *(float4*)&out[(size_t)row * DM + t * 4] = o;
}

// ---------------------------------------------------------------------------
extern "C" void kernel_launch(void* const* d_in, const int* in_sizes, int n_in,
                              void* d_out, int out_size)
{
    const float* v_in  = (const float*)d_in[0];
    const float* k_in  = (const float*)d_in[1];
    const float* q_in  = (const float*)d_in[2];
    const void*  mask  = d_in[3];
    const float* w_q   = (const float*)d_in[4];
    const float* w_k   = (const float*)d_in[5];
    const float* w_v   = (const float*)d_in[6];
    const float* w_o   = (const float*)d_in[7];
    const float* b_o   = (const float*)d_in[8];
    const float* gamma = (const float*)d_in[9];
    const float* beta  = (const float*)d_in[10];
    float* out = (float*)d_out;

    cudaFuncSetAttribute(proj_kernel, cudaFuncAttributeMaxDynamicSharedMemorySize, GEMM_SMEM);
    cudaFuncSetAttribute(outproj_kernel, cudaFuncAttributeMaxDynamicSharedMemorySize, GEMM_SMEM);

    sniff_mask_kernel<<<1, 256>>>((const unsigned int*)mask, 16384);
    pack_mask_kernel<<<2048, 256>>>(mask);
    f2h_all_kernel<<<dim3(256, 7), 256>>>(q_in, k_in, v_in, w_q, w_k, w_v, w_o);

    proj_kernel<<<dim3(NH / 2, MROWS / 128, 3), 256, GEMM_SMEM>>>();
    attn_kernel<<<dim3(SLQ / 128, NH * BB), 256>>>();
    outproj_kernel<<<dim3(DM / 128, MROWS / 128), 256, GEMM_SMEM>>>(k_in, b_o);
    ln_kernel<<<MROWS, 256>>>(gamma, beta, out);
}

// round 10
// speedup vs baseline: 6.1521x; 1.0013x over previous
#include <cuda_runtime.h>
#include <cuda_fp16.h>
#include <cstdint>

#define BB 2
#define SLQ 2048
#define SLK 2048
#define DM 1024
#define NH 16
#define DH 64
#define MROWS (BB*SLQ)   // 4096

// Scratch (allocation-free rule: device globals)
__device__ __half g_qh[NH*BB*SLQ*DH];
__device__ __half g_kh[NH*BB*SLK*DH];
__device__ __half g_vh[NH*BB*SLK*DH];
__device__ __half g_oh[NH*BB*SLQ*DH];
__device__ __half g_xq[MROWS*DM];
__device__ __half g_xk[MROWS*DM];
__device__ __half g_xv[MROWS*DM];
__device__ __half g_wq[NH*DM*DH];
__device__ __half g_wk[NH*DM*DH];
__device__ __half g_wv[NH*DM*DH];
__device__ __half g_wo[DM*DM];
__device__ float  g_x [MROWS*DM];
__device__ unsigned int g_mbits[BB*SLQ*(SLK/32)];

// ---------------------------------------------------------------------------
__device__ __forceinline__ unsigned pack2(float a, float b) {
    __half2 h = __floats2half2_rn(a, b);
    return *(unsigned*)&h;
}

__device__ __forceinline__ unsigned ex2h2(unsigned x) {
    unsigned r;
    asm("ex2.approx.f16x2 %0, %1;" : "=r"(r) : "r"(x));
    return r;
}

__device__ __forceinline__ float ex2f(float x) {
    float r;
    asm("ex2.approx.f32 %0, %1;" : "=f"(r) : "f"(x));
    return r;
}

__device__ __forceinline__ void mma16816(float* c,
    unsigned a0, unsigned a1, unsigned a2, unsigned a3,
    unsigned b0, unsigned b1)
{
    asm volatile(
        "mma.sync.aligned.m16n8k16.row.col.f32.f16.f16.f32 "
        "{%0,%1,%2,%3}, {%4,%5,%6,%7}, {%8,%9}, {%0,%1,%2,%3};"
        : "+f"(c[0]), "+f"(c[1]), "+f"(c[2]), "+f"(c[3])
        : "r"(a0), "r"(a1), "r"(a2), "r"(a3), "r"(b0), "r"(b1));
}

__device__ __forceinline__ void ldsm4(unsigned& r0, unsigned& r1,
                                      unsigned& r2, unsigned& r3, unsigned addr)
{
    asm volatile("ldmatrix.sync.aligned.m8n8.x4.shared.b16 {%0,%1,%2,%3}, [%4];"
        : "=r"(r0), "=r"(r1), "=r"(r2), "=r"(r3) : "r"(addr));
}

__device__ __forceinline__ void ldsm4t(unsigned& r0, unsigned& r1,
                                       unsigned& r2, unsigned& r3, unsigned addr)
{
    asm volatile("ldmatrix.sync.aligned.m8n8.x4.trans.shared.b16 {%0,%1,%2,%3}, [%4];"
        : "=r"(r0), "=r"(r1), "=r"(r2), "=r"(r3) : "r"(addr));
}

__device__ __forceinline__ void cp16(unsigned smem, const void* gptr)
{
    asm volatile("cp.async.cg.shared.global [%0], [%1], 16;" :: "r"(smem), "l"(gptr));
}
__device__ __forceinline__ void cp_commit() { asm volatile("cp.async.commit_group;"); }
__device__ __forceinline__ void cp_wait0()  { asm volatile("cp.async.wait_group 0;"); }

// ---------------------------------------------------------------------------
// Pack mask into bits (bit=1 -> masked/-inf). Per-block inline dtype sniff:
// int32 bool data has every 32-bit word in {0,1}; uint8 bool data (p=0.5 ones)
// has a >1 word in the first 16K words with probability 1 - 2^-huge.
// ---------------------------------------------------------------------------
__global__ void pack_mask_kernel(const void* __restrict__ mraw)
{
    __shared__ int s_u8;
    const int lane = threadIdx.x & 31;
    if (threadIdx.x == 0) s_u8 = 0;
    __syncthreads();
    {
        const unsigned int* mw = (const unsigned int*)mraw;
        int found = 0;
        for (int i = threadIdx.x; i < 16384; i += blockDim.x)
            if (mw[i] > 1u) { found = 1; break; }
        if (found) s_u8 = 1;
    }
    __syncthreads();
    const bool u8 = (s_u8 != 0);

    const int nwords = BB * SLQ * (SLK / 32);
    int gw = (blockIdx.x * blockDim.x + threadIdx.x) >> 5;
    const int stride = (gridDim.x * blockDim.x) >> 5;
    for (int w = gw; w < nwords; w += stride) {
        int idx = w * 32 + lane;
        int v = u8 ? (int)((const unsigned char*)mraw)[idx]
                   : ((const int*)mraw)[idx];
        unsigned int bits = __ballot_sync(0xffffffffu, v != 0);
        if (lane == 0) g_mbits[w] = bits;
    }
}

// Fused fp32 -> fp16 prepack for all 7 tensors. grid.y = region.
__global__ void f2h_all_kernel(
    const float* __restrict__ s0, const float* __restrict__ s1,
    const float* __restrict__ s2, const float* __restrict__ s3,
    const float* __restrict__ s4, const float* __restrict__ s5,
    const float* __restrict__ s6)
{
    const float* src;
    __half* dst;
    int n;
    switch (blockIdx.y) {
        case 0: src = s0; dst = g_xq; n = MROWS * DM; break;
        case 1: src = s1; dst = g_xk; n = MROWS * DM; break;
        case 2: src = s2; dst = g_xv; n = MROWS * DM; break;
        case 3: src = s3; dst = g_wq; n = NH * DM * DH; break;
        case 4: src = s4; dst = g_wk; n = NH * DM * DH; break;
        case 5: src = s5; dst = g_wv; n = NH * DM * DH; break;
        default: src = s6; dst = g_wo; n = DM * DM; break;
    }
    int i = (blockIdx.x * blockDim.x + threadIdx.x) * 4;
    int stride = gridDim.x * blockDim.x * 4;
    for (; i < n; i += stride) {
        float4 v = *(const float4*)&src[i];
        *(uint2*)&dst[i] = make_uint2(pack2(v.x, v.y), pack2(v.z, v.w));
    }
}

// ---------------------------------------------------------------------------
// Projection GEMM (fp16 mma): C[h,b,l,e] = sum_d X[b,l,d]*W[h,d,e]
// Block 128(M) x 128(N = 2 heads), k-tile 64, cp.async double buffered.
// ---------------------------------------------------------------------------
#define ASZ (128*72)
#define BSZ (64*136)
#define GEMM_SMEM ((2*ASZ + 2*BSZ) * 2)

__global__ __launch_bounds__(256, 2) void proj_kernel()
{
    extern __shared__ __half dsm[];
    __half* Asm = dsm;
    __half* Bsm = dsm + 2 * ASZ;

    const __half* __restrict__ X;
    const __half* __restrict__ W;
    __half* __restrict__ C;
    if (blockIdx.z == 0)      { X = g_xq; W = g_wq; C = g_qh; }
    else if (blockIdx.z == 1) { X = g_xk; W = g_wk; C = g_kh; }
    else                      { X = g_xv; W = g_wv; C = g_vh; }

    const int t = threadIdx.x;
    const int warp = t >> 5, lane = t & 31;
    const int g = lane >> 2, tq = lane & 3;
    const int wm = warp >> 2, wn = warp & 3;
    const int mBase = blockIdx.y * 128;
    const int h0 = blockIdx.x * 2;

    const int i8 = lane & 7, sel = lane >> 3;
    const int rowF = ((sel & 1) << 3) + i8;
    const int colF = (sel >> 1) << 3;
    const unsigned aSm = (unsigned)__cvta_generic_to_shared(Asm);
    const unsigned bSm = (unsigned)__cvta_generic_to_shared(Bsm);

    float acc[4][4][4];
    #pragma unroll
    for (int mt = 0; mt < 4; mt++)
        #pragma unroll
        for (int nt = 0; nt < 4; nt++)
            #pragma unroll
            for (int i = 0; i < 4; i++) acc[mt][nt][i] = 0.f;

    const int arow = t >> 3, aseg = (t & 7) * 8;
    const int brow = t >> 4, bseg = (t & 15) * 8;

    auto stage = [&](int kt, int buf) {
        #pragma unroll
        for (int it = 0; it < 4; it++) {
            int row = arow + it * 32;
            cp16(aSm + ((buf * 128 + row) * 72 + aseg) * 2,
                 &X[(size_t)(mBase + row) * DM + kt + aseg]);
        }
        #pragma unroll
        for (int it = 0; it < 4; it++) {
            int row = brow + it * 16;
            int head = h0 + (bseg >> 6), e = bseg & 63;
            cp16(bSm + ((buf * 64 + row) * 136 + bseg) * 2,
                 &W[((size_t)head * DM + kt + row) * DH + e]);
        }
        cp_commit();
    };

    stage(0, 0);
    const int NKT = DM / 64;  // 16
    for (int it = 0; it < NKT; it++) {
        cp_wait0();
        __syncthreads();
        if (it + 1 < NKT) stage((it + 1) * 64, (it + 1) & 1);
        const int abuf = (it & 1) * 128, bbuf = (it & 1) * 64;

        #pragma unroll
        for (int ks = 0; ks < 4; ks++) {
            unsigned af[4][4];
            #pragma unroll
            for (int mt = 0; mt < 4; mt++)
                ldsm4(af[mt][0], af[mt][1], af[mt][2], af[mt][3],
                      aSm + ((abuf + wm * 64 + mt * 16 + rowF) * 72 + ks * 16 + colF) * 2);
            #pragma unroll
            for (int ntp = 0; ntp < 2; ntp++) {
                unsigned b0, b1, b2, b3;
                ldsm4t(b0, b1, b2, b3,
                       bSm + ((bbuf + ks * 16 + rowF) * 136 + wn * 32 + ntp * 16 + colF) * 2);
                #pragma unroll
                for (int mt = 0; mt < 4; mt++) {
                    mma16816(acc[mt][ntp * 2],     af[mt][0], af[mt][1], af[mt][2], af[mt][3], b0, b1);
                    mma16816(acc[mt][ntp * 2 + 1], af[mt][0], af[mt][1], af[mt][2], af[mt][3], b2, b3);
                }
            }
        }
    }

    #pragma unroll
    for (int mt = 0; mt < 4; mt++) {
        int r0 = mBase + wm * 64 + mt * 16 + g;
        int r1 = r0 + 8;
        int b0i = r0 >> 11, l0 = r0 & 2047;
        int b1i = r1 >> 11, l1 = r1 & 2047;
        #pragma unroll
        for (int nt = 0; nt < 4; nt++) {
            int n = wn * 32 + nt * 8 + tq * 2;
            int head = h0 + (n >> 6), e = n & 63;
            __half* c0 = C + (((size_t)(head * BB + b0i) << 11) + l0) * DH;
            __half* c1 = C + (((size_t)(head * BB + b1i) << 11) + l1) * DH;
            *(unsigned*)&c0[e] = pack2(acc[mt][nt][0], acc[mt][nt][1]);
            *(unsigned*)&c1[e] = pack2(acc[mt][nt][2], acc[mt][nt][3]);
        }
    }
}

// ---------------------------------------------------------------------------
// Output projection: g_x = Ocat @ Wo + bo + resid (fp32 out)
// ---------------------------------------------------------------------------
__global__ __launch_bounds__(256, 2) void outproj_kernel(
    const float* __restrict__ resid, const float* __restrict__ bo)
{
    extern __shared__ __half dsm[];
    __half* Asm = dsm;
    __half* Bsm = dsm + 2 * ASZ;

    const int t = threadIdx.x;
    const int warp = t >> 5, lane = t & 31;
    const int g = lane >> 2, tq = lane & 3;
    const int wm = warp >> 2, wn = warp & 3;
    const int mBase = blockIdx.y * 128;
    const int nBase = blockIdx.x * 128;

    const int i8 = lane & 7, sel = lane >> 3;
    const int rowF = ((sel & 1) << 3) + i8;
    const int colF = (sel >> 1) << 3;
    const unsigned aSm = (unsigned)__cvta_generic_to_shared(Asm);
    const unsigned bSm = (unsigned)__cvta_generic_to_shared(Bsm);

    float acc[4][4][4];
    #pragma unroll
    for (int mt = 0; mt < 4; mt++)
        #pragma unroll
        for (int nt = 0; nt < 4; nt++)
            #pragma unroll
            for (int i = 0; i < 4; i++) acc[mt][nt][i] = 0.f;

    const int arow = t >> 3, aseg = (t & 7) * 8;
    const int brow = t >> 4, bseg = (t & 15) * 8;

    auto stage = [&](int kt, int buf) {
        const int kh = kt >> 6;
        #pragma unroll
        for (int it = 0; it < 4; it++) {
            int row = arow + it * 32;
            int m = mBase + row;
            int mb = m >> 11, ml = m & 2047;
            cp16(aSm + ((buf * 128 + row) * 72 + aseg) * 2,
                 &g_oh[(((size_t)(kh * BB + mb) << 11) + ml) * DH + aseg]);
        }
        #pragma unroll
        for (int it = 0; it < 4; it++) {
            int row = brow + it * 16;
            cp16(bSm + ((buf * 64 + row) * 136 + bseg) * 2,
                 &g_wo[(size_t)(kt + row) * DM + nBase + bseg]);
        }
        cp_commit();
    };

    stage(0, 0);
    const int NKT = DM / 64;
    for (int it = 0; it < NKT; it++) {
        cp_wait0();
        __syncthreads();
        if (it + 1 < NKT) stage((it + 1) * 64, (it + 1) & 1);
        const int abuf = (it & 1) * 128, bbuf = (it & 1) * 64;

        #pragma unroll
        for (int ks = 0; ks < 4; ks++) {
            unsigned af[4][4];
            #pragma unroll
            for (int mt = 0; mt < 4; mt++)
                ldsm4(af[mt][0], af[mt][1], af[mt][2], af[mt][3],
                      aSm + ((abuf + wm * 64 + mt * 16 + rowF) * 72 + ks * 16 + colF) * 2);
            #pragma unroll
            for (int ntp = 0; ntp < 2; ntp++) {
                unsigned b0, b1, b2, b3;
                ldsm4t(b0, b1, b2, b3,
                       bSm + ((bbuf + ks * 16 + rowF) * 136 + wn * 32 + ntp * 16 + colF) * 2);
                #pragma unroll
                for (int mt = 0; mt < 4; mt++) {
                    mma16816(acc[mt][ntp * 2],     af[mt][0], af[mt][1], af[mt][2], af[mt][3], b0, b1);
                    mma16816(acc[mt][ntp * 2 + 1], af[mt][0], af[mt][1], af[mt][2], af[mt][3], b2, b3);
                }
            }
        }
    }

    #pragma unroll
    for (int mt = 0; mt < 4; mt++) {
        int r0 = mBase + wm * 64 + mt * 16 + g;
        int r1 = r0 + 8;
        #pragma unroll
        for (int nt = 0; nt < 4; nt++) {
            int n = nBase + wn * 32 + nt * 8 + tq * 2;
            float2 bb = *(const float2*)&bo[n];
            float2 rA = *(const float2*)&resid[(size_t)r0 * DM + n];
            float2 rB = *(const float2*)&resid[(size_t)r1 * DM + n];
            *(float2*)&g_x[(size_t)r0 * DM + n] =
                make_float2(acc[mt][nt][0] + bb.x + rA.x, acc[mt][nt][1] + bb.y + rA.y);
            *(float2*)&g_x[(size_t)r1 * DM + n] =
                make_float2(acc[mt][nt][2] + bb.x + rB.x, acc[mt][nt][3] + bb.y + rB.y);
        }
    }
}

// ---------------------------------------------------------------------------
// Flash attention (fp16 mma, cp.async, f16x2 exp2 softmax).
// ---------------------------------------------------------------------------
__global__ __launch_bounds__(256, 2) void attn_kernel()
{
    __shared__ __half Ks[2][64][72];
    __shared__ __half Vs[2][64][72];

    const int t = threadIdx.x;
    const int warp = t >> 5, lane = t & 31;
    const int g = lane >> 2, tq = lane & 3;
    const int hb = blockIdx.y;
    const int b = hb & 1;
    const int qBase = blockIdx.x * 128;

    const __half* __restrict__ Q = g_qh + (size_t)hb * SLQ * DH;
    const __half* __restrict__ K = g_kh + (size_t)hb * SLK * DH;
    const __half* __restrict__ V = g_vh + (size_t)hb * SLK * DH;
    __half* __restrict__ O = g_oh + (size_t)hb * SLQ * DH;

    const int r0 = qBase + warp * 16 + g;
    const int r1 = r0 + 8;

    unsigned qf[4][4];
    #pragma unroll
    for (int ks = 0; ks < 4; ks++) {
        qf[ks][0] = *(const unsigned*)&Q[(size_t)r0 * DH + ks * 16 + 2 * tq];
        qf[ks][1] = *(const unsigned*)&Q[(size_t)r1 * DH + ks * 16 + 2 * tq];
        qf[ks][2] = *(const unsigned*)&Q[(size_t)r0 * DH + ks * 16 + 8 + 2 * tq];
        qf[ks][3] = *(const unsigned*)&Q[(size_t)r1 * DH + ks * 16 + 8 + 2 * tq];
    }

    const int i8 = lane & 7, sel = lane >> 3;
    const int rowK = ((sel >> 1) << 3) + i8;
    const int colK = (sel & 1) << 3;
    const int rowV = ((sel & 1) << 3) + i8;
    const int colV = (sel >> 1) << 3;
    const unsigned kSm = (unsigned)__cvta_generic_to_shared(&Ks[0][0][0]);
    const unsigned vSm = (unsigned)__cvta_generic_to_shared(&Vs[0][0][0]);
    const unsigned kAddr0 = kSm + (rowK * 72 + colK) * 2;
    const unsigned vAddr0 = vSm + (rowV * 72 + colV) * 2;
    const unsigned BUFB = 64 * 72 * 2;

    float oc[8][4];
    #pragma unroll
    for (int dt = 0; dt < 8; dt++)
        #pragma unroll
        for (int i = 0; i < 4; i++) oc[dt][i] = 0.f;
    float m0 = -1e30f, m1 = -1e30f, l0 = 0.f, l1 = 0.f;

    const float c = 0.18033688011112042f;  // (1/8) * log2(e)
    const unsigned* mb0 = &g_mbits[((size_t)(b << 11) + r0) * 64];
    const unsigned* mb1 = &g_mbits[((size_t)(b << 11) + r1) * 64];

    const int srow = t >> 3, sseg = (t & 7) * 8;

    auto stage = [&](int kb, int buf) {
        #pragma unroll
        for (int it = 0; it < 2; it++) {
            int row = srow + it * 32;
            cp16(kSm + ((buf * 64 + row) * 72 + sseg) * 2,
                 &K[(size_t)(kb + row) * DH + sseg]);
            cp16(vSm + ((buf * 64 + row) * 72 + sseg) * 2,
                 &V[(size_t)(kb + row) * DH + sseg]);
        }
        cp_commit();
    };

    stage(0, 0);
    const int NT = SLK / 64;
    for (int it = 0; it < NT; it++) {
        cp_wait0();
        __syncthreads();
        if (it + 1 < NT) stage((it + 1) * 64, (it + 1) & 1);
        const unsigned kA = kAddr0 + (it & 1) * BUFB;
        const unsigned vA = vAddr0 + (it & 1) * BUFB;
        const int kb = it * 64;

        float sc[8][4];
        #pragma unroll
        for (int nt = 0; nt < 8; nt++)
            #pragma unroll
            for (int i = 0; i < 4; i++) sc[nt][i] = 0.f;

        #pragma unroll
        for (int ks = 0; ks < 4; ks++) {
            #pragma unroll
            for (int ntp = 0; ntp < 4; ntp++) {
                unsigned b0, b1, b2, b3;
                ldsm4(b0, b1, b2, b3, kA + (ntp * 16 * 72 + ks * 16) * 2);
                mma16816(sc[ntp * 2],     qf[ks][0], qf[ks][1], qf[ks][2], qf[ks][3], b0, b1);
                mma16816(sc[ntp * 2 + 1], qf[ks][0], qf[ks][1], qf[ks][2], qf[ks][3], b2, b3);
            }
        }

        uint2 w0 = *(const uint2*)&mb0[kb >> 5];
        uint2 w1 = *(const uint2*)&mb1[kb >> 5];
        unsigned long long mm0 = (unsigned long long)w0.x | ((unsigned long long)w0.y << 32);
        unsigned long long mm1 = (unsigned long long)w1.x | ((unsigned long long)w1.y << 32);
        #pragma unroll
        for (int nt = 0; nt < 8; nt++) {
            int c0 = nt * 8 + tq * 2, c1 = c0 + 1;
            sc[nt][0] = ((mm0 >> c0) & 1ULL) ? -1e30f : sc[nt][0] * c;
            sc[nt][1] = ((mm0 >> c1) & 1ULL) ? -1e30f : sc[nt][1] * c;
            sc[nt][2] = ((mm1 >> c0) & 1ULL) ? -1e30f : sc[nt][2] * c;
            sc[nt][3] = ((mm1 >> c1) & 1ULL) ? -1e30f : sc[nt][3] * c;
        }

        float mx0 = -1e30f, mx1 = -1e30f;
        #pragma unroll
        for (int nt = 0; nt < 8; nt++) {
            mx0 = fmaxf(mx0, fmaxf(sc[nt][0], sc[nt][1]));
            mx1 = fmaxf(mx1, fmaxf(sc[nt][2], sc[nt][3]));
        }
        mx0 = fmaxf(mx0, __shfl_xor_sync(0xffffffffu, mx0, 1));
        mx0 = fmaxf(mx0, __shfl_xor_sync(0xffffffffu, mx0, 2));
        mx1 = fmaxf(mx1, __shfl_xor_sync(0xffffffffu, mx1, 1));
        mx1 = fmaxf(mx1, __shfl_xor_sync(0xffffffffu, mx1, 2));

        float newm0 = fmaxf(m0, mx0), newm1 = fmaxf(m1, mx1);
        float al0 = ex2f(m0 - newm0), al1 = ex2f(m1 - newm1);
        m0 = newm0; m1 = newm1;

        unsigned pf[8][2];
        __half2 hs0 = __floats2half2_rn(0.f, 0.f);
        __half2 hs1 = hs0;
        #pragma unroll
        for (int nt = 0; nt < 8; nt++) {
            pf[nt][0] = ex2h2(pack2(sc[nt][0] - newm0, sc[nt][1] - newm0));
            pf[nt][1] = ex2h2(pack2(sc[nt][2] - newm1, sc[nt][3] - newm1));
            hs0 = __hadd2(hs0, *(__half2*)&pf[nt][0]);
            hs1 = __hadd2(hs1, *(__half2*)&pf[nt][1]);
        }
        float2 f0 = __half22float2(hs0);
        float2 f1 = __half22float2(hs1);
        float rs0 = f0.x + f0.y, rs1 = f1.x + f1.y;
        rs0 += __shfl_xor_sync(0xffffffffu, rs0, 1);
        rs0 += __shfl_xor_sync(0xffffffffu, rs0, 2);
        rs1 += __shfl_xor_sync(0xffffffffu, rs1, 1);
        rs1 += __shfl_xor_sync(0xffffffffu, rs1, 2);
        l0 = l0 * al0 + rs0;
        l1 = l1 * al1 + rs1;

        #pragma unroll
        for (int dt = 0; dt < 8; dt++) {
            oc[dt][0] *= al0; oc[dt][1] *= al0;
            oc[dt][2] *= al1; oc[dt][3] *= al1;
        }

        #pragma unroll
        for (int ks = 0; ks < 4; ks++) {
            unsigned a0 = pf[2 * ks][0], a1 = pf[2 * ks][1];
            unsigned a2 = pf[2 * ks + 1][0], a3 = pf[2 * ks + 1][1];
            #pragma unroll
            for (int dtp = 0; dtp < 4; dtp++) {
                unsigned b0, b1, b2, b3;
                ldsm4t(b0, b1, b2, b3, vA + (ks * 16 * 72 + dtp * 16) * 2);
                mma16816(oc[dtp * 2],     a0, a1, a2, a3, b0, b1);
                mma16816(oc[dtp * 2 + 1], a0, a1, a2, a3, b2, b3);
            }
        }
    }

    float inv0 = 1.f / l0, inv1 = 1.f / l1;
    #pragma unroll
    for (int dt = 0; dt < 8; dt++) {
        int d = dt * 8 + tq * 2;
        *(unsigned*)&O[(size_t)r0 * DH + d] = pack2(oc[dt][0] * inv0, oc[dt][1] * inv0);
        *(unsigned*)&O[(size_t)r1 * DH + d] = pack2(oc[dt][2] * inv1, oc[dt][3] * inv1);
    }
}

// ---------------------------------------------------------------------------
// LayerNorm (ddof=1, eps on std)
// ---------------------------------------------------------------------------
__global__ __launch_bounds__(256) void ln_kernel(
    const float* __restrict__ gamma, const float* __restrict__ beta,
    float* __restrict__ out)
{
    __shared__ float red[8];
    const int row = blockIdx.x;
    const int t = threadIdx.x;
    const float* x = g_x + (size_t)row * DM;

    float4 v = *(const float4*)&x[t * 4];
    float s = v.x + v.y + v.z + v.w;
    #pragma unroll
    for (int sft = 16; sft >= 1; sft >>= 1)
        s += __shfl_xor_sync(0xffffffffu, s, sft);
    if ((t & 31) == 0) red[t >> 5] = s;
    __syncthreads();
    float tot = 0.f;
    #pragma unroll
    for (int w = 0; w < 8; w++) tot += red[w];
    float mean = tot * (1.0f / DM);
    __syncthreads();

    float d0 = v.x - mean, d1 = v.y - mean, d2 = v.z - mean, d3 = v.w - mean;
    float sq = d0 * d0 + d1 * d1 + d2 * d2 + d3 * d3;
    #pragma unroll
    for (int sft = 16; sft >= 1; sft >>= 1)
        sq += __shfl_xor_sync(0xffffffffu, sq, sft);
    if ((t & 31) == 0) red[t >> 5] = sq;
    __syncthreads();
    float sqt = 0.f;
    #pragma unroll
    for (int w = 0; w < 8; w++) sqt += red[w];
    float stdv = sqrtf(sqt * (1.0f / (DM - 1)));
    float inv = 1.0f / (stdv + 1e-3f);

    float4 gm = *(const float4*)&gamma[t * 4];
    float4 be = *(const float4*)&beta[t * 4];
    float4 o;
    o.x = d0 * inv * gm.x + be.x;
    o.y = d1 * inv * gm.y + be.y;
    o.z = d2 * inv * gm.z + be.z;
    o.w = d3 * inv * gm.w + be.w;
    *(float4*)&out[(size_t)row * DM + t * 4] = o;
}

// ---------------------------------------------------------------------------
extern "C" void kernel_launch(void* const* d_in, const int* in_sizes, int n_in,
                              void* d_out, int out_size)
{
    const float* v_in  = (const float*)d_in[0];
    const float* k_in  = (const float*)d_in[1];
    const float* q_in  = (const float*)d_in[2];
    const void*  mask  = d_in[3];
    const float* w_q   = (const float*)d_in[4];
    const float* w_k   = (const float*)d_in[5];
    const float* w_v   = (const float*)d_in[6];
    const float* w_o   = (const float*)d_in[7];
    const float* b_o   = (const float*)d_in[8];
    const float* gamma = (const float*)d_in[9];
    const float* beta  = (const float*)d_in[10];
    float* out = (float*)d_out;

    cudaFuncSetAttribute(proj_kernel, cudaFuncAttributeMaxDynamicSharedMemorySize, GEMM_SMEM);
    cudaFuncSetAttribute(outproj_kernel, cudaFuncAttributeMaxDynamicSharedMemorySize, GEMM_SMEM);

    pack_mask_kernel<<<2048, 256>>>(mask);
    f2h_all_kernel<<<dim3(512, 7), 256>>>(q_in, k_in, v_in, w_q, w_k, w_v, w_o);

    proj_kernel<<<dim3(NH / 2, MROWS / 128, 3), 256, GEMM_SMEM>>>();
    attn_kernel<<<dim3(SLQ / 128, NH * BB), 256>>>();
    outproj_kernel<<<dim3(DM / 128, MROWS / 128), 256, GEMM_SMEM>>>(k_in, b_o);
    ln_kernel<<<MROWS, 256>>>(gamma, beta, out);
}